// round 9
// baseline (speedup 1.0000x reference)
#include <cuda_runtime.h>
#include <cuda_bf16.h>
#include <math.h>
#include <stdint.h>

// Problem shapes (fixed by the dataset)
#define B_   8
#define HW_  32
#define T_   31
#define NF_  256
#define E_   512
#define M_   2048
#define H_   8
#define DH_  64

#define ROWS_Q   (B_ * NF_)            // 2048
#define ROWS_KV  (B_ * T_ * NF_)       // 63488

// tgemm2 tiling (small GEMMs): CTA 128x128, 3-stage, 4 warps
#define TK 32
#define NSTAGE 3
#define STAGE_BYTES 32768
#define SMEM_TOTAL (NSTAGE * STAGE_BYTES)

// tgemm4 tiling (big GEMMs): CTA 128x256, 4-stage, 8 warps
#define NSTAGE4 4
#define STAGE4_BYTES 49152             // A 16KB + B 32KB
#define SMEM4_TOTAL (NSTAGE4 * STAGE4_BYTES)   // 196608

// Attention smem layout (floats, row stride 72)
#define AQ_OFF 0
#define AP_OFF (256*72)
#define AK_OFF (512*72)
#define AV_OFF (512*72 + 2*64*72)
#define ATTN_SMEM ((512*72 + 4*64*72) * 4)   // 221184 bytes

// ---------------- static scratch (allocation-free rule) ----------------
__device__ float g_qln [ (size_t)ROWS_Q  * E_ ];
__device__ float g_q   [ (size_t)ROWS_Q  * E_ ];
__device__ float g_kvln[ (size_t)ROWS_KV * E_ ];
__device__ float g_kv  [ (size_t)ROWS_KV * 1024 ];
__device__ float g_t1  [ (size_t)ROWS_KV * E_ ];
__device__ float g_t2  [ (size_t)ROWS_KV * E_ ];
__device__ float g_hid [ (size_t)ROWS_KV * M_ ];
__device__ float g_wtA [ (size_t)4 * E_ * E_ ];   // wkvT(1024x512) + woT
__device__ float g_wtB [ (size_t)4 * E_ * M_ ];   // mlpq_w1T mlpq_w2T mlp_w1T mlp_w2T
__device__ float g_wqT [ (size_t)E_ * E_ ];
__device__ float g_bkv [ 1024 ];

// ---------------- helpers ----------------
__device__ __forceinline__ float gelu_exact(float x) {
    return 0.5f * x * (1.0f + erff(x * 0.70710678118654752f));
}
__device__ __forceinline__ float tf32r(float x) {
    uint32_t r;
    asm("cvt.rna.tf32.f32 %0, %1;" : "=r"(r) : "f"(x));
    return __uint_as_float(r);
}
__device__ __forceinline__ uint32_t smem_u32(const void* p) {
    uint32_t a;
    asm("{ .reg .u64 t; cvta.to.shared.u64 t, %1; cvt.u32.u64 %0, t; }" : "=r"(a) : "l"(p));
    return a;
}
__device__ __forceinline__ void cp16(uint32_t s, const void* g) {
    asm volatile("cp.async.cg.shared.global [%0], [%1], 16;" :: "r"(s), "l"(g));
}
__device__ __forceinline__ void ldsm4(uint32_t* r, uint32_t a) {
    asm volatile("ldmatrix.sync.aligned.m8n8.x4.shared.b16 {%0,%1,%2,%3}, [%4];"
        : "=r"(r[0]), "=r"(r[1]), "=r"(r[2]), "=r"(r[3]) : "r"(a));
}
__device__ __forceinline__ void mma_tf32(float* d, const uint32_t* a, const uint32_t* b) {
    asm volatile(
        "mma.sync.aligned.m16n8k8.row.col.f32.tf32.tf32.f32 "
        "{%0,%1,%2,%3}, {%4,%5,%6,%7}, {%8,%9}, {%0,%1,%2,%3};"
        : "+f"(d[0]), "+f"(d[1]), "+f"(d[2]), "+f"(d[3])
        : "r"(a[0]), "r"(a[1]), "r"(a[2]), "r"(a[3]), "r"(b[0]), "r"(b[1]));
}

__device__ __forceinline__ float blk_sum(float v, float* sb) {
    #pragma unroll
    for (int o = 16; o; o >>= 1) v += __shfl_xor_sync(0xffffffffu, v, o);
    if ((threadIdx.x & 31) == 0) sb[threadIdx.x >> 5] = v;
    __syncthreads();
    float r = sb[0] + sb[1] + sb[2] + sb[3];
    __syncthreads();
    return r;
}

// ---------------- batched weight transpose (+ tf32 rounding) + bias concat ----------------
struct TSeg { const float* W; float* WT; int K; int N; int blk0; };
struct TDesc { TSeg s[8]; const float* bk; const float* bv; float* bkv; };

__global__ void __launch_bounds__(256) transpose_all(TDesc d, int nblk_transpose)
{
    __shared__ float t[32][33];
    int blk = blockIdx.x;
    if (blk >= nblk_transpose) {                 // bias concat block
        int i = threadIdx.x;
        #pragma unroll
        for (int j = 0; j < 4; j++) {
            int idx = i + j * 256;
            d.bkv[idx] = (idx < 512) ? d.bk[idx] : d.bv[idx - 512];
        }
        return;
    }
    int si = 0;
    #pragma unroll
    for (int j = 1; j < 8; j++) if (blk >= d.s[j].blk0) si = j;
    const TSeg sg = d.s[si];
    int b = blk - sg.blk0;
    int nx = sg.N >> 5;
    int n0 = (b % nx) * 32, k0 = (b / nx) * 32;
    int tx = threadIdx.x & 31, ty = threadIdx.x >> 5;
    #pragma unroll
    for (int j = 0; j < 32; j += 8)
        t[ty + j][tx] = sg.W[(size_t)(k0 + ty + j) * sg.N + n0 + tx];
    __syncthreads();
    #pragma unroll
    for (int j = 0; j < 32; j += 8)
        sg.WT[(size_t)(n0 + ty + j) * sg.K + k0 + tx] = tf32r(t[tx][ty + j]);
}

// ---------------- LN of input, split into q-path (t==0) and kv-path ----------------
__global__ void __launch_bounds__(128) ln_in_kernel(
    const float* __restrict__ X,
    const float* __restrict__ gq,  const float* __restrict__ bq,
    const float* __restrict__ gkv, const float* __restrict__ bkv,
    float* __restrict__ out_q, float* __restrict__ out_kv)
{
    __shared__ float sb[4];
    int r = blockIdx.x;
    int b = r >> 13;
    int t = (r >> 8) & 31;
    int n = r & 255;
    int c = threadIdx.x * 4;

    float4 xv = *(const float4*)(X + (size_t)r * E_ + c);
    float s = xv.x + xv.y + xv.z + xv.w;
    float mean = blk_sum(s, sb) * (1.0f / E_);
    float d0 = xv.x - mean, d1 = xv.y - mean, d2 = xv.z - mean, d3 = xv.w - mean;
    float var = blk_sum(d0*d0 + d1*d1 + d2*d2 + d3*d3, sb) * (1.0f / E_);
    float rs = rsqrtf(var + 1e-6f);

    const float *g, *be; float* dst;
    if (t == 0) { g = gq;  be = bq;  dst = out_q  + ((size_t)(b * NF_ + n)) * E_; }
    else        { g = gkv; be = bkv; dst = out_kv + ((size_t)((b * T_ + (t - 1)) * NF_ + n)) * E_; }

    float4 gg = *(const float4*)(g + c);
    float4 bb = *(const float4*)(be + c);
    float4 y;
    y.x = tf32r(d0 * rs * gg.x + bb.x);
    y.y = tf32r(d1 * rs * gg.y + bb.y);
    y.z = tf32r(d2 * rs * gg.z + bb.z);
    y.w = tf32r(d3 * rs * gg.w + bb.w);
    *(float4*)(dst + c) = y;
}

// ---------------- fused double LayerNorm, rounded output ----------------
__global__ void __launch_bounds__(128) dual_ln_kernel(
    const float* __restrict__ X,
    const float* __restrict__ g1, const float* __restrict__ b1,
    const float* __restrict__ g2, const float* __restrict__ b2,
    float* __restrict__ Y)
{
    __shared__ float sb[4];
    size_t r = blockIdx.x;
    int c = threadIdx.x * 4;
    float4 xv = *(const float4*)(X + r * E_ + c);

    float s = xv.x + xv.y + xv.z + xv.w;
    float mean = blk_sum(s, sb) * (1.0f / E_);
    float d0 = xv.x - mean, d1 = xv.y - mean, d2 = xv.z - mean, d3 = xv.w - mean;
    float var = blk_sum(d0*d0 + d1*d1 + d2*d2 + d3*d3, sb) * (1.0f / E_);
    float rs = rsqrtf(var + 1e-6f);

    float4 gg = *(const float4*)(g1 + c);
    float4 bb = *(const float4*)(b1 + c);
    float y0 = d0 * rs * gg.x + bb.x;
    float y1 = d1 * rs * gg.y + bb.y;
    float y2 = d2 * rs * gg.z + bb.z;
    float y3 = d3 * rs * gg.w + bb.w;

    float s2 = y0 + y1 + y2 + y3;
    float mean2 = blk_sum(s2, sb) * (1.0f / E_);
    float e0 = y0 - mean2, e1 = y1 - mean2, e2 = y2 - mean2, e3 = y3 - mean2;
    float var2 = blk_sum(e0*e0 + e1*e1 + e2*e2 + e3*e3, sb) * (1.0f / E_);
    float rs2 = rsqrtf(var2 + 1e-6f);

    float4 gg2 = *(const float4*)(g2 + c);
    float4 bb2 = *(const float4*)(b2 + c);
    float4 out;
    out.x = tf32r(e0 * rs2 * gg2.x + bb2.x);
    out.y = tf32r(e1 * rs2 * gg2.y + bb2.y);
    out.z = tf32r(e2 * rs2 * gg2.z + bb2.z);
    out.w = tf32r(e3 * rs2 * gg2.w + bb2.w);
    *(float4*)(Y + r * E_ + c) = out;
}

// ---------------- tgemm2: 128x128 tile (small GEMMs) ----------------
template<bool DO_GELU, bool DO_RES, bool DO_ROUND>
__global__ void __launch_bounds__(128, 2) tgemm2(
    const float* __restrict__ A, const float* __restrict__ BT,
    const float* __restrict__ bias, const float* __restrict__ res,
    float* __restrict__ C, int Mrows, int N, int K)
{
    extern __shared__ char dsm[];
    const uint32_t sb0 = smem_u32(dsm);
    const int tid = threadIdx.x, warp = tid >> 5, lane = tid & 31;
    const int brow = blockIdx.y * 128;
    const int bcol = blockIdx.x * 128;
    const int wm = (warp >> 1) * 64, wn = (warp & 1) * 64;

    const int rf = tid >> 3, gf = tid & 7;
    const uint32_t fso = (uint32_t)rf * 128 + ((gf ^ (rf & 7)) << 4);
    const float* gA = A  + (size_t)(brow + rf) * K + gf * 4;
    const float* gB = BT + (size_t)(bcol + rf) * K + gf * 4;

    const int r7 = lane & 7, tile = lane >> 3;
    const int arow = (tile & 1) * 8 + r7;
    const int ah   = tile >> 1;
    const int bnr  = (tile >> 1) * 8 + r7;
    const int bh   = tile & 1;

    float acc[4][8][4];
    #pragma unroll
    for (int mi = 0; mi < 4; mi++)
        #pragma unroll
        for (int ni = 0; ni < 8; ni++)
            #pragma unroll
            for (int r = 0; r < 4; r++) acc[mi][ni][r] = 0.0f;

    const int nkt = K / TK;

    auto fill = [&](int kt) {
        const int st = kt % NSTAGE;
        uint32_t dA = sb0 + st * STAGE_BYTES;
        uint32_t dB = dA + 16384;
        const float* ga = gA + kt * TK;
        const float* gb = gB + kt * TK;
        #pragma unroll
        for (int i = 0; i < 8; i++) {
            uint32_t so = fso + (uint32_t)i * 2048;
            cp16(dA + so, ga + (size_t)i * 16 * K);
            cp16(dB + so, gb + (size_t)i * 16 * K);
        }
        asm volatile("cp.async.commit_group;" ::: "memory");
    };

    fill(0);
    if (nkt > 1) fill(1);

    for (int kt = 0; kt < nkt; kt++) {
        if (kt + 1 < nkt) asm volatile("cp.async.wait_group 1;" ::: "memory");
        else              asm volatile("cp.async.wait_group 0;" ::: "memory");
        __syncthreads();
        if (kt + 2 < nkt) fill(kt + 2);

        const int st = kt % NSTAGE;
        const uint32_t sA = sb0 + st * STAGE_BYTES;
        const uint32_t sB = sA + 16384;

        #pragma unroll
        for (int ks = 0; ks < 4; ks++) {
            uint32_t af[4][4], bq[4][4];
            #pragma unroll
            for (int mi = 0; mi < 4; mi++) {
                int row = wm + mi * 16 + arow;
                uint32_t ad = sA + (uint32_t)row * 128 + ((((ks << 1) | ah) ^ r7) << 4);
                ldsm4(af[mi], ad);
            }
            #pragma unroll
            for (int n2 = 0; n2 < 4; n2++) {
                int nr = wn + n2 * 16 + bnr;
                uint32_t bd = sB + (uint32_t)nr * 128 + ((((ks << 1) | bh) ^ r7) << 4);
                ldsm4(bq[n2], bd);
            }
            #pragma unroll
            for (int mi = 0; mi < 4; mi++)
                #pragma unroll
                for (int ni = 0; ni < 8; ni++)
                    mma_tf32(acc[mi][ni], af[mi], &bq[ni >> 1][(ni & 1) * 2]);
        }
    }

    const int g = lane >> 2, q = lane & 3;
    #pragma unroll
    for (int ni = 0; ni < 8; ni++) {
        int col = bcol + wn + ni * 8 + q * 2;
        float bb0 = bias[col], bb1 = bias[col + 1];
        #pragma unroll
        for (int mi = 0; mi < 4; mi++) {
            #pragma unroll
            for (int h = 0; h < 2; h++) {
                int row = brow + wm + mi * 16 + g + h * 8;
                size_t off = (size_t)row * N + col;
                float v0 = acc[mi][ni][h * 2 + 0] + bb0;
                float v1 = acc[mi][ni][h * 2 + 1] + bb1;
                if (DO_RES) {
                    float2 rr = *(const float2*)(res + off);
                    v0 += rr.x; v1 += rr.y;
                }
                if (DO_GELU) { v0 = gelu_exact(v0); v1 = gelu_exact(v1); }
                if (DO_ROUND) { v0 = tf32r(v0); v1 = tf32r(v1); }
                float2 o; o.x = v0; o.y = v1;
                *(float2*)(C + off) = o;
            }
        }
    }
}

// ---------------- tgemm4: 128x256 tile, 256 threads, 4-stage (big GEMMs) ----------------
// Same 64x64 warp tile / fragment path; warp grid 2x4. A 16KB + B 32KB per stage.
template<bool DO_GELU, bool DO_RES, bool DO_ROUND>
__global__ void __launch_bounds__(256, 1) tgemm4(
    const float* __restrict__ A, const float* __restrict__ BT,
    const float* __restrict__ bias, const float* __restrict__ res,
    float* __restrict__ C, int Mrows, int N, int K)
{
    extern __shared__ char dsm[];
    const uint32_t sb0 = smem_u32(dsm);
    const int tid = threadIdx.x, warp = tid >> 5, lane = tid & 31;
    const int brow = blockIdx.y * 128;
    const int bcol = blockIdx.x * 256;
    const int wm = (warp >> 2) * 64, wn = (warp & 3) * 64;

    // fill mapping: 256 threads; rows covered in 32-row strides, granule = tid&7
    const int rf = tid >> 3, gf = tid & 7;                      // rf 0..31
    const uint32_t fso = (uint32_t)rf * 128 + ((gf ^ (rf & 7)) << 4);  // + i*4096
    const float* gA = A  + (size_t)(brow + rf) * K + gf * 4;
    const float* gB = BT + (size_t)(bcol + rf) * K + gf * 4;

    const int r7 = lane & 7, tile = lane >> 3;
    const int arow = (tile & 1) * 8 + r7;
    const int ah   = tile >> 1;
    const int bnr  = (tile >> 1) * 8 + r7;
    const int bh   = tile & 1;

    float acc[4][8][4];
    #pragma unroll
    for (int mi = 0; mi < 4; mi++)
        #pragma unroll
        for (int ni = 0; ni < 8; ni++)
            #pragma unroll
            for (int r = 0; r < 4; r++) acc[mi][ni][r] = 0.0f;

    const int nkt = K / TK;

    // guarded fill: out-of-range -> empty commit (keeps group counts uniform)
    auto fill = [&](int kt) {
        if (kt < nkt) {
            const int st = kt & (NSTAGE4 - 1);
            uint32_t dA = sb0 + st * STAGE4_BYTES;
            uint32_t dB = dA + 16384;
            const float* ga = gA + kt * TK;
            const float* gb = gB + kt * TK;
            #pragma unroll
            for (int i = 0; i < 4; i++)                         // A: 128 rows
                cp16(dA + fso + (uint32_t)i * 4096, ga + (size_t)i * 32 * K);
            #pragma unroll
            for (int i = 0; i < 8; i++)                         // B: 256 rows
                cp16(dB + fso + (uint32_t)i * 4096, gb + (size_t)i * 32 * K);
        }
        asm volatile("cp.async.commit_group;" ::: "memory");
    };

    fill(0); fill(1); fill(2);

    for (int kt = 0; kt < nkt; kt++) {
        asm volatile("cp.async.wait_group 2;" ::: "memory");
        __syncthreads();
        fill(kt + 3);

        const int st = kt & (NSTAGE4 - 1);
        const uint32_t sA = sb0 + st * STAGE4_BYTES;
        const uint32_t sB = sA + 16384;

        #pragma unroll
        for (int ks = 0; ks < 4; ks++) {
            uint32_t af[4][4], bq[4][4];
            #pragma unroll
            for (int mi = 0; mi < 4; mi++) {
                int row = wm + mi * 16 + arow;
                uint32_t ad = sA + (uint32_t)row * 128 + ((((ks << 1) | ah) ^ r7) << 4);
                ldsm4(af[mi], ad);
            }
            #pragma unroll
            for (int n2 = 0; n2 < 4; n2++) {
                int nr = wn + n2 * 16 + bnr;
                uint32_t bd = sB + (uint32_t)nr * 128 + ((((ks << 1) | bh) ^ r7) << 4);
                ldsm4(bq[n2], bd);
            }
            #pragma unroll
            for (int mi = 0; mi < 4; mi++)
                #pragma unroll
                for (int ni = 0; ni < 8; ni++)
                    mma_tf32(acc[mi][ni], af[mi], &bq[ni >> 1][(ni & 1) * 2]);
        }
    }

    const int g = lane >> 2, q = lane & 3;
    #pragma unroll
    for (int ni = 0; ni < 8; ni++) {
        int col = bcol + wn + ni * 8 + q * 2;
        float bb0 = bias[col], bb1 = bias[col + 1];
        #pragma unroll
        for (int mi = 0; mi < 4; mi++) {
            #pragma unroll
            for (int h = 0; h < 2; h++) {
                int row = brow + wm + mi * 16 + g + h * 8;
                size_t off = (size_t)row * N + col;
                float v0 = acc[mi][ni][h * 2 + 0] + bb0;
                float v1 = acc[mi][ni][h * 2 + 1] + bb1;
                if (DO_RES) {
                    float2 rr = *(const float2*)(res + off);
                    v0 += rr.x; v1 += rr.y;
                }
                if (DO_GELU) { v0 = gelu_exact(v0); v1 = gelu_exact(v1); }
                if (DO_ROUND) { v0 = tf32r(v0); v1 = tf32r(v1); }
                float2 o; o.x = v0; o.y = v1;
                *(float2*)(C + off) = o;
            }
        }
    }
}

// ---------------- tensorized flash attention (tf32 mma) ----------------
__global__ void __launch_bounds__(256, 1) attn_mma(
    const float* __restrict__ Q, const float* __restrict__ KV, float* __restrict__ O)
{
    extern __shared__ float sm[];
    float* Qs = sm + AQ_OFF;
    float* Ps = sm + AP_OFF;
    float* Ks = sm + AK_OFF;
    float* Vs = sm + AV_OFF;

    const int idx = blockIdx.x;
    const int h = idx & 7;
    const int bt = idx >> 3;
    const int b = bt / T_;
    const int tid = threadIdx.x, warp = tid >> 5, lane = tid & 31;
    const int g = lane >> 2, q = lane & 3;
    const int wm = warp * 32;

    {
        const float* gq = Q + (size_t)(b * NF_) * E_ + h * DH_;
        #pragma unroll
        for (int i = tid; i < 256 * 16; i += 256) {
            int r = i >> 4, c4 = (i & 15) * 4;
            float4 v = *(const float4*)(gq + (size_t)r * E_ + c4);
            float* d = Qs + r * 72 + c4;
            d[0] = v.x * 0.125f; d[1] = v.y * 0.125f;
            d[2] = v.z * 0.125f; d[3] = v.w * 0.125f;
        }
    }

    const float* kvbase = KV + (size_t)bt * NF_ * 1024 + h * DH_;
    auto fillkv = [&](int ch) {
        int st = ch & 1;
        #pragma unroll
        for (int i = tid; i < 64 * 16; i += 256) {
            int r = i >> 4, c4 = (i & 15) * 4;
            const float* src = kvbase + (size_t)(ch * 64 + r) * 1024 + c4;
            cp16(smem_u32(Ks + (st * 64 + r) * 72 + c4), src);
            cp16(smem_u32(Vs + (st * 64 + r) * 72 + c4), src + 512);
        }
        asm volatile("cp.async.commit_group;" ::: "memory");
    };

    fillkv(0);

    float o[2][8][4];
    #pragma unroll
    for (int mi = 0; mi < 2; mi++)
        #pragma unroll
        for (int nd = 0; nd < 8; nd++)
            #pragma unroll
            for (int r = 0; r < 4; r++) o[mi][nd][r] = 0.0f;
    float mrow[2][2] = {{-1e30f, -1e30f}, {-1e30f, -1e30f}};
    float lrow[2][2] = {{0.0f, 0.0f}, {0.0f, 0.0f}};

    for (int ch = 0; ch < 4; ch++) {
        asm volatile("cp.async.wait_group 0;" ::: "memory");
        __syncthreads();
        if (ch + 1 < 4) fillkv(ch + 1);

        const float* Kst = Ks + (ch & 1) * 64 * 72;
        const float* Vst = Vs + (ch & 1) * 64 * 72;

        float s[2][8][4];
        #pragma unroll
        for (int mi = 0; mi < 2; mi++)
            #pragma unroll
            for (int ni = 0; ni < 8; ni++)
                #pragma unroll
                for (int r = 0; r < 4; r++) s[mi][ni][r] = 0.0f;

        #pragma unroll
        for (int ks = 0; ks < 8; ks++) {
            uint32_t af[2][4], bf[8][2];
            #pragma unroll
            for (int mi = 0; mi < 2; mi++) {
                const float* qp = Qs + (wm + mi * 16 + g) * 72 + ks * 8 + q;
                af[mi][0] = __float_as_uint(qp[0]);
                af[mi][1] = __float_as_uint(qp[8 * 72]);
                af[mi][2] = __float_as_uint(qp[4]);
                af[mi][3] = __float_as_uint(qp[8 * 72 + 4]);
            }
            #pragma unroll
            for (int ni = 0; ni < 8; ni++) {
                const float* kp = Kst + (ni * 8 + g) * 72 + ks * 8 + q;
                bf[ni][0] = __float_as_uint(kp[0]);
                bf[ni][1] = __float_as_uint(kp[4]);
            }
            #pragma unroll
            for (int mi = 0; mi < 2; mi++)
                #pragma unroll
                for (int ni = 0; ni < 8; ni++)
                    mma_tf32(s[mi][ni], af[mi], bf[ni]);
        }

        #pragma unroll
        for (int mi = 0; mi < 2; mi++) {
            #pragma unroll
            for (int hh = 0; hh < 2; hh++) {
                float rm = -1e30f;
                #pragma unroll
                for (int ni = 0; ni < 8; ni++)
                    rm = fmaxf(rm, fmaxf(s[mi][ni][hh * 2], s[mi][ni][hh * 2 + 1]));
                rm = fmaxf(rm, __shfl_xor_sync(0xffffffffu, rm, 1));
                rm = fmaxf(rm, __shfl_xor_sync(0xffffffffu, rm, 2));
                float mnew = fmaxf(mrow[mi][hh], rm);
                float alpha = __expf(mrow[mi][hh] - mnew);
                mrow[mi][hh] = mnew;
                float rs = 0.0f;
                #pragma unroll
                for (int ni = 0; ni < 8; ni++) {
                    float p0 = __expf(s[mi][ni][hh * 2]     - mnew);
                    float p1 = __expf(s[mi][ni][hh * 2 + 1] - mnew);
                    rs += p0 + p1;
                    s[mi][ni][hh * 2]     = p0;
                    s[mi][ni][hh * 2 + 1] = p1;
                }
                rs += __shfl_xor_sync(0xffffffffu, rs, 1);
                rs += __shfl_xor_sync(0xffffffffu, rs, 2);
                lrow[mi][hh] = lrow[mi][hh] * alpha + rs;
                #pragma unroll
                for (int nd = 0; nd < 8; nd++) {
                    o[mi][nd][hh * 2]     *= alpha;
                    o[mi][nd][hh * 2 + 1] *= alpha;
                }
            }
        }

        __syncwarp();
        #pragma unroll
        for (int mi = 0; mi < 2; mi++) {
            #pragma unroll
            for (int ni = 0; ni < 8; ni++) {
                float* pp = Ps + (wm + mi * 16 + g) * 72 + ni * 8 + 2 * q;
                pp[0]          = tf32r(s[mi][ni][0]);
                pp[1]          = tf32r(s[mi][ni][1]);
                pp[8 * 72]     = tf32r(s[mi][ni][2]);
                pp[8 * 72 + 1] = tf32r(s[mi][ni][3]);
            }
        }
        __syncwarp();

        #pragma unroll
        for (int ks = 0; ks < 8; ks++) {
            uint32_t af[2][4], bf[8][2];
            #pragma unroll
            for (int mi = 0; mi < 2; mi++) {
                const float* pp = Ps + (wm + mi * 16 + g) * 72 + ks * 8 + q;
                af[mi][0] = __float_as_uint(pp[0]);
                af[mi][1] = __float_as_uint(pp[8 * 72]);
                af[mi][2] = __float_as_uint(pp[4]);
                af[mi][3] = __float_as_uint(pp[8 * 72 + 4]);
            }
            #pragma unroll
            for (int nd = 0; nd < 8; nd++) {
                const float* vp = Vst + (ks * 8 + q) * 72 + nd * 8 + g;
                bf[nd][0] = __float_as_uint(vp[0]);
                bf[nd][1] = __float_as_uint(vp[4 * 72]);
            }
            #pragma unroll
            for (int mi = 0; mi < 2; mi++)
                #pragma unroll
                for (int nd = 0; nd < 8; nd++)
                    mma_tf32(o[mi][nd], af[mi], bf[nd]);
        }
        __syncwarp();
    }

    #pragma unroll
    for (int mi = 0; mi < 2; mi++) {
        #pragma unroll
        for (int hh = 0; hh < 2; hh++) {
            float inv = 1.0f / lrow[mi][hh];
            int row = wm + mi * 16 + g + hh * 8;
            float* orow = O + ((size_t)bt * NF_ + row) * E_ + h * DH_;
            #pragma unroll
            for (int nd = 0; nd < 8; nd++) {
                float2 ov;
                ov.x = tf32r(o[mi][nd][hh * 2]     * inv);
                ov.y = tf32r(o[mi][nd][hh * 2 + 1] * inv);
                *(float2*)(orow + nd * 8 + 2 * q) = ov;
            }
        }
    }
}

// ---------------- host ----------------
extern "C" void kernel_launch(void* const* d_in, const int* in_sizes, int n_in,
                              void* d_out, int out_size)
{
    const float* inputs  = (const float*)d_in[0];
    const float* wq      = (const float*)d_in[1];
    const float* wk      = (const float*)d_in[2];
    const float* wv      = (const float*)d_in[3];
    const float* bq      = (const float*)d_in[4];
    const float* bk      = (const float*)d_in[5];
    const float* bv      = (const float*)d_in[6];
    const float* wo      = (const float*)d_in[7];
    const float* bo      = (const float*)d_in[8];
    const float* lnq_g   = (const float*)d_in[9];
    const float* lnq_b   = (const float*)d_in[10];
    const float* lnkv_g  = (const float*)d_in[11];
    const float* lnkv_b  = (const float*)d_in[12];
    const float* mlpq_w1 = (const float*)d_in[13];
    const float* mlpq_b1 = (const float*)d_in[14];
    const float* mlpq_w2 = (const float*)d_in[15];
    const float* mlpq_b2 = (const float*)d_in[16];
    const float* resln_g = (const float*)d_in[17];
    const float* resln_b = (const float*)d_in[18];
    const float* ln2_g   = (const float*)d_in[19];
    const float* ln2_b   = (const float*)d_in[20];
    const float* mlp_w1  = (const float*)d_in[21];
    const float* mlp_b1  = (const float*)d_in[22];
    const float* mlp_w2  = (const float*)d_in[23];
    const float* mlp_b2  = (const float*)d_in[24];
    float* out = (float*)d_out;

    float *qln, *q, *kvln, *kv, *t1, *t2, *hid, *wtA, *wtB, *wqT, *bkvC;
    cudaGetSymbolAddress((void**)&qln,  g_qln);
    cudaGetSymbolAddress((void**)&q,    g_q);
    cudaGetSymbolAddress((void**)&kvln, g_kvln);
    cudaGetSymbolAddress((void**)&kv,   g_kv);
    cudaGetSymbolAddress((void**)&t1,   g_t1);
    cudaGetSymbolAddress((void**)&t2,   g_t2);
    cudaGetSymbolAddress((void**)&hid,  g_hid);
    cudaGetSymbolAddress((void**)&wtA,  g_wtA);
    cudaGetSymbolAddress((void**)&wtB,  g_wtB);
    cudaGetSymbolAddress((void**)&wqT,  g_wqT);
    cudaGetSymbolAddress((void**)&bkvC, g_bkv);

    float* wkvT = wtA;                            // 1024 x 512
    float* woT  = wtA + (size_t)2 * E_ * E_;
    float* mq1T = wtB;                            // (M, E)
    float* mq2T = wtB + (size_t)E_ * M_;          // (E, M)
    float* m1T  = wtB + (size_t)2 * E_ * M_;      // (M, E)
    float* m2T  = wtB + (size_t)3 * E_ * M_;      // (E, M)

    cudaFuncSetAttribute(tgemm2<false,false,true >, cudaFuncAttributeMaxDynamicSharedMemorySize, SMEM_TOTAL);
    cudaFuncSetAttribute(tgemm4<false,false,false>, cudaFuncAttributeMaxDynamicSharedMemorySize, SMEM4_TOTAL);
    cudaFuncSetAttribute(tgemm4<false,false,true >, cudaFuncAttributeMaxDynamicSharedMemorySize, SMEM4_TOTAL);
    cudaFuncSetAttribute(tgemm4<true ,false,true >, cudaFuncAttributeMaxDynamicSharedMemorySize, SMEM4_TOTAL);
    cudaFuncSetAttribute(tgemm4<false,true ,false>, cudaFuncAttributeMaxDynamicSharedMemorySize, SMEM4_TOTAL);
    cudaFuncSetAttribute(attn_mma, cudaFuncAttributeMaxDynamicSharedMemorySize, ATTN_SMEM);

    TDesc td;
    int off = 0;
    auto seg = [&](int i, const float* W, float* WT, int K, int N) {
        td.s[i].W = W; td.s[i].WT = WT; td.s[i].K = K; td.s[i].N = N; td.s[i].blk0 = off;
        off += (N / 32) * (K / 32);
    };
    seg(0, wk,      wkvT,                    E_, E_);
    seg(1, wv,      wkvT + (size_t)E_ * E_,  E_, E_);
    seg(2, wq,      wqT,                     E_, E_);
    seg(3, wo,      woT,                     E_, E_);
    seg(4, mlpq_w1, mq1T,                    E_, M_);
    seg(5, mlpq_w2, mq2T,                    M_, E_);
    seg(6, mlp_w1,  m1T,                     E_, M_);
    seg(7, mlp_w2,  m2T,                     M_, E_);
    td.bk = bk; td.bv = bv; td.bkv = bkvC;
    const int nblk_t = off;

    // 1) input LN
    ln_in_kernel<<<B_ * HW_ * NF_, 128>>>(inputs, lnq_g, lnq_b, lnkv_g, lnkv_b, qln, kvln);
    // 2) all weight transposes + bias concat in ONE launch
    transpose_all<<<nblk_t + 1, 256>>>(td, nblk_t);
    // 3) q projection (small -> tgemm2)
    tgemm2<false,false,true ><<<dim3(E_/128, ROWS_Q/128), 128, SMEM_TOTAL>>>(qln, wqT, bq, nullptr, q, ROWS_Q, E_, E_);
    // 4) fused k|v projection (N=1024)  <-- ncu slot
    tgemm4<false,false,true ><<<dim3(1024/256, ROWS_KV/128), 256, SMEM4_TOTAL>>>(kvln, wkvT, bkvC, nullptr, kv, ROWS_KV, 1024, E_);
    // 5) attention -> t1
    attn_mma<<<B_ * T_ * H_, 256, ATTN_SMEM>>>(q, kv, t1);
    // 6) out projection -> t2
    tgemm4<false,false,true ><<<dim3(E_/256, ROWS_KV/128), 256, SMEM4_TOTAL>>>(t1, woT, bo, nullptr, t2, ROWS_KV, E_, E_);
    // 7-8) mlp_q
    tgemm4<true ,false,true ><<<dim3(M_/256, ROWS_KV/128), 256, SMEM4_TOTAL>>>(t2, mq1T, mlpq_b1, nullptr, hid, ROWS_KV, M_, E_);
    tgemm4<false,true ,false><<<dim3(E_/256, ROWS_KV/128), 256, SMEM4_TOTAL>>>(hid, mq2T, mlpq_b2, kvln,  t1,  ROWS_KV, E_, M_);
    // 9) res_ln + ln_2
    dual_ln_kernel<<<ROWS_KV, 128>>>(t1, resln_g, resln_b, ln2_g, ln2_b, t2);
    // 10-11) final MLP
    tgemm4<true ,false,true ><<<dim3(M_/256, ROWS_KV/128), 256, SMEM4_TOTAL>>>(t2,  m1T, mlp_b1, nullptr, hid, ROWS_KV, M_, E_);
    tgemm4<false,false,false><<<dim3(E_/256, ROWS_KV/128), 256, SMEM4_TOTAL>>>(hid, m2T, mlp_b2, nullptr, out, ROWS_KV, E_, M_);
}

// round 10
// speedup vs baseline: 1.2849x; 1.2849x over previous
#include <cuda_runtime.h>
#include <cuda_fp16.h>
#include <math.h>
#include <stdint.h>

// Problem shapes
#define B_   8
#define HW_  32
#define T_   31
#define NF_  256
#define E_   512
#define M_   2048
#define H_   8
#define DH_  64

#define ROWS_Q   (B_ * NF_)            // 2048
#define ROWS_KV  (B_ * T_ * NF_)       // 63488

// hgemm tiling: CTA 128x128, K-chunk 64 (fp16), 3-stage, 4 warps of 64x64
#define TK 64
#define NSTAGE 3
#define STAGE_BYTES 32768              // A 16KB + B 16KB (fp16)
#define SMEM_TOTAL (NSTAGE * STAGE_BYTES)   // 98304

// Attention smem (bytes): Qs 32K, Ps 32K, Ks 16K, Vs 16K
#define AQ_B 0
#define AP_B 32768
#define AK_B 65536
#define AV_B 81920
#define ATTN_SMEM 98304

// ---------------- static scratch ----------------
__device__ __half g_qln [ (size_t)ROWS_Q  * E_ ];
__device__ __half g_q   [ (size_t)ROWS_Q  * E_ ];
__device__ __half g_kvln[ (size_t)ROWS_KV * E_ ];
__device__ __half g_kv  [ (size_t)ROWS_KV * 1024 ];
__device__ __half g_t1h [ (size_t)ROWS_KV * E_ ];
__device__ __half g_t2h [ (size_t)ROWS_KV * E_ ];
__device__ __half g_hid [ (size_t)ROWS_KV * M_ ];
__device__ float  g_t1f [ (size_t)ROWS_KV * E_ ];
__device__ __half g_wtA [ (size_t)4 * E_ * E_ ];   // wkvT(1024x512) + woT
__device__ __half g_wtB [ (size_t)4 * E_ * M_ ];   // mq1T mq2T m1T m2T
__device__ __half g_wqT [ (size_t)E_ * E_ ];
__device__ float  g_bkv [ 1024 ];

// ---------------- helpers ----------------
__device__ __forceinline__ float gelu_exact(float x) {
    return 0.5f * x * (1.0f + erff(x * 0.70710678118654752f));
}
__device__ __forceinline__ uint32_t smem_u32(const void* p) {
    uint32_t a;
    asm("{ .reg .u64 t; cvta.to.shared.u64 t, %1; cvt.u32.u64 %0, t; }" : "=r"(a) : "l"(p));
    return a;
}
__device__ __forceinline__ void cp16(uint32_t s, const void* g) {
    asm volatile("cp.async.cg.shared.global [%0], [%1], 16;" :: "r"(s), "l"(g));
}
__device__ __forceinline__ void ldsm4(uint32_t* r, uint32_t a) {
    asm volatile("ldmatrix.sync.aligned.m8n8.x4.shared.b16 {%0,%1,%2,%3}, [%4];"
        : "=r"(r[0]), "=r"(r[1]), "=r"(r[2]), "=r"(r[3]) : "r"(a));
}
__device__ __forceinline__ void ldsm4t(uint32_t* r, uint32_t a) {
    asm volatile("ldmatrix.sync.aligned.m8n8.x4.trans.shared.b16 {%0,%1,%2,%3}, [%4];"
        : "=r"(r[0]), "=r"(r[1]), "=r"(r[2]), "=r"(r[3]) : "r"(a));
}
// mma m16n8k16 f16 inputs, f32 accumulate
__device__ __forceinline__ void mma_f16(float* d, const uint32_t* a, uint32_t b0, uint32_t b1) {
    asm volatile(
        "mma.sync.aligned.m16n8k16.row.col.f32.f16.f16.f32 "
        "{%0,%1,%2,%3}, {%4,%5,%6,%7}, {%8,%9}, {%0,%1,%2,%3};"
        : "+f"(d[0]), "+f"(d[1]), "+f"(d[2]), "+f"(d[3])
        : "r"(a[0]), "r"(a[1]), "r"(a[2]), "r"(a[3]), "r"(b0), "r"(b1));
}

__device__ __forceinline__ float blk_sum(float v, float* sb) {
    #pragma unroll
    for (int o = 16; o; o >>= 1) v += __shfl_xor_sync(0xffffffffu, v, o);
    if ((threadIdx.x & 31) == 0) sb[threadIdx.x >> 5] = v;
    __syncthreads();
    float r = sb[0] + sb[1] + sb[2] + sb[3];
    __syncthreads();
    return r;
}

// ---------------- batched weight transpose -> fp16, + bias concat ----------------
struct TSeg { const float* W; __half* WT; int K; int N; int blk0; };
struct TDesc { TSeg s[8]; const float* bk; const float* bv; float* bkv; };

__global__ void __launch_bounds__(256) transpose_all(TDesc d, int nblk_transpose)
{
    __shared__ float t[32][33];
    int blk = blockIdx.x;
    if (blk >= nblk_transpose) {
        int i = threadIdx.x;
        #pragma unroll
        for (int j = 0; j < 4; j++) {
            int idx = i + j * 256;
            d.bkv[idx] = (idx < 512) ? d.bk[idx] : d.bv[idx - 512];
        }
        return;
    }
    int si = 0;
    #pragma unroll
    for (int j = 1; j < 8; j++) if (blk >= d.s[j].blk0) si = j;
    const TSeg sg = d.s[si];
    int b = blk - sg.blk0;
    int nx = sg.N >> 5;
    int n0 = (b % nx) * 32, k0 = (b / nx) * 32;
    int tx = threadIdx.x & 31, ty = threadIdx.x >> 5;
    #pragma unroll
    for (int j = 0; j < 32; j += 8)
        t[ty + j][tx] = sg.W[(size_t)(k0 + ty + j) * sg.N + n0 + tx];
    __syncthreads();
    #pragma unroll
    for (int j = 0; j < 32; j += 8)
        sg.WT[(size_t)(n0 + ty + j) * sg.K + k0 + tx] = __float2half_rn(t[tx][ty + j]);
}

// ---------------- LN of input -> fp16 outputs ----------------
__global__ void __launch_bounds__(128) ln_in_kernel(
    const float* __restrict__ X,
    const float* __restrict__ gq,  const float* __restrict__ bq,
    const float* __restrict__ gkv, const float* __restrict__ bkv,
    __half* __restrict__ out_q, __half* __restrict__ out_kv)
{
    __shared__ float sb[4];
    int r = blockIdx.x;
    int b = r >> 13;
    int t = (r >> 8) & 31;
    int n = r & 255;
    int c = threadIdx.x * 4;

    float4 xv = *(const float4*)(X + (size_t)r * E_ + c);
    float s = xv.x + xv.y + xv.z + xv.w;
    float mean = blk_sum(s, sb) * (1.0f / E_);
    float d0 = xv.x - mean, d1 = xv.y - mean, d2 = xv.z - mean, d3 = xv.w - mean;
    float var = blk_sum(d0*d0 + d1*d1 + d2*d2 + d3*d3, sb) * (1.0f / E_);
    float rs = rsqrtf(var + 1e-6f);

    const float *g, *be; __half* dst;
    if (t == 0) { g = gq;  be = bq;  dst = out_q  + ((size_t)(b * NF_ + n)) * E_; }
    else        { g = gkv; be = bkv; dst = out_kv + ((size_t)((b * T_ + (t - 1)) * NF_ + n)) * E_; }

    float4 gg = *(const float4*)(g + c);
    float4 bb = *(const float4*)(be + c);
    __half2 h0 = __floats2half2_rn(d0 * rs * gg.x + bb.x, d1 * rs * gg.y + bb.y);
    __half2 h1 = __floats2half2_rn(d2 * rs * gg.z + bb.z, d3 * rs * gg.w + bb.w);
    uint2 u; u.x = *(uint32_t*)&h0; u.y = *(uint32_t*)&h1;
    *(uint2*)(dst + c) = u;
}

// ---------------- fused double LayerNorm: float in -> fp16 out ----------------
__global__ void __launch_bounds__(128) dual_ln_kernel(
    const float* __restrict__ X,
    const float* __restrict__ g1, const float* __restrict__ b1,
    const float* __restrict__ g2, const float* __restrict__ b2,
    __half* __restrict__ Y)
{
    __shared__ float sb[4];
    size_t r = blockIdx.x;
    int c = threadIdx.x * 4;
    float4 xv = *(const float4*)(X + r * E_ + c);

    float s = xv.x + xv.y + xv.z + xv.w;
    float mean = blk_sum(s, sb) * (1.0f / E_);
    float d0 = xv.x - mean, d1 = xv.y - mean, d2 = xv.z - mean, d3 = xv.w - mean;
    float var = blk_sum(d0*d0 + d1*d1 + d2*d2 + d3*d3, sb) * (1.0f / E_);
    float rs = rsqrtf(var + 1e-6f);

    float4 gg = *(const float4*)(g1 + c);
    float4 bb = *(const float4*)(b1 + c);
    float y0 = d0 * rs * gg.x + bb.x;
    float y1 = d1 * rs * gg.y + bb.y;
    float y2 = d2 * rs * gg.z + bb.z;
    float y3 = d3 * rs * gg.w + bb.w;

    float s2 = y0 + y1 + y2 + y3;
    float mean2 = blk_sum(s2, sb) * (1.0f / E_);
    float e0 = y0 - mean2, e1 = y1 - mean2, e2 = y2 - mean2, e3 = y3 - mean2;
    float var2 = blk_sum(e0*e0 + e1*e1 + e2*e2 + e3*e3, sb) * (1.0f / E_);
    float rs2 = rsqrtf(var2 + 1e-6f);

    float4 gg2 = *(const float4*)(g2 + c);
    float4 bb2 = *(const float4*)(b2 + c);
    __half2 h0 = __floats2half2_rn(e0 * rs2 * gg2.x + bb2.x, e1 * rs2 * gg2.y + bb2.y);
    __half2 h1 = __floats2half2_rn(e2 * rs2 * gg2.z + bb2.z, e3 * rs2 * gg2.w + bb2.w);
    uint2 u; u.x = *(uint32_t*)&h0; u.y = *(uint32_t*)&h1;
    *(uint2*)(Y + r * E_ + c) = u;
}

// ---------------- fp16 mma GEMM: C = epi(A @ BT^T + bias [+res]) ----------------
// A: Mrows x K fp16 row-major. BT: N x K fp16 row-major. 128x128 tile, TK=64,
// 3-stage cp.async, 4 warps (2x2) of 64x64, m16n8k16, fp32 accum.
template<bool DO_GELU, bool DO_RES, typename OT>
__global__ void __launch_bounds__(128, 2) hgemm(
    const __half* __restrict__ A, const __half* __restrict__ BT,
    const float* __restrict__ bias, const __half* __restrict__ res,
    OT* __restrict__ C, int Mrows, int N, int K)
{
    extern __shared__ char dsm[];
    const uint32_t sb0 = smem_u32(dsm);
    const int tid = threadIdx.x, warp = tid >> 5, lane = tid & 31;
    const int brow = blockIdx.y * 128;
    const int bcol = blockIdx.x * 128;
    const int wm = (warp >> 1) * 64, wn = (warp & 1) * 64;

    // fill: 128 rows x 8 granules (16B = 8 fp16). rf 0..15 (+16i), gf 0..7
    const int rf = tid >> 3, gf = tid & 7;
    const uint32_t fso = (uint32_t)rf * 128 + ((gf ^ (rf & 7)) << 4);
    const __half* gA = A  + (size_t)(brow + rf) * K + gf * 8;
    const __half* gB = BT + (size_t)(bcol + rf) * K + gf * 8;

    float acc[4][8][4];
    #pragma unroll
    for (int mi = 0; mi < 4; mi++)
        #pragma unroll
        for (int ni = 0; ni < 8; ni++)
            #pragma unroll
            for (int r = 0; r < 4; r++) acc[mi][ni][r] = 0.0f;

    const int nkt = K / TK;

    auto fill = [&](int kt) {
        const int st = kt % NSTAGE;
        uint32_t dA = sb0 + st * STAGE_BYTES;
        uint32_t dB = dA + 16384;
        const __half* ga = gA + kt * TK;
        const __half* gb = gB + kt * TK;
        #pragma unroll
        for (int i = 0; i < 8; i++) {
            uint32_t so = fso + (uint32_t)i * 2048;       // 16 rows * 128B
            cp16(dA + so, ga + (size_t)i * 16 * K);
            cp16(dB + so, gb + (size_t)i * 16 * K);
        }
        asm volatile("cp.async.commit_group;" ::: "memory");
    };

    fill(0);
    if (nkt > 1) fill(1);

    for (int kt = 0; kt < nkt; kt++) {
        if (kt + 1 < nkt) asm volatile("cp.async.wait_group 1;" ::: "memory");
        else              asm volatile("cp.async.wait_group 0;" ::: "memory");
        __syncthreads();
        if (kt + 2 < nkt) fill(kt + 2);

        const int st = kt % NSTAGE;
        const uint32_t sA = sb0 + st * STAGE_BYTES;
        const uint32_t sB = sA + 16384;

        #pragma unroll
        for (int ks = 0; ks < 4; ks++) {               // 4 x k16
            uint32_t af[4][4], bq[4][4];
            #pragma unroll
            for (int mi = 0; mi < 4; mi++) {
                int row = wm + mi * 16 + (lane & 15);
                uint32_t kg = (uint32_t)(ks * 2 + (lane >> 4));
                ldsm4(af[mi], sA + (uint32_t)row * 128 + ((kg ^ (row & 7)) << 4));
            }
            #pragma unroll
            for (int nt = 0; nt < 4; nt++) {
                int nr = wn + nt * 16 + ((lane >> 4) << 3) + (lane & 7);
                uint32_t kg = (uint32_t)(ks * 2 + ((lane >> 3) & 1));
                ldsm4(bq[nt], sB + (uint32_t)nr * 128 + ((kg ^ (nr & 7)) << 4));
            }
            #pragma unroll
            for (int mi = 0; mi < 4; mi++)
                #pragma unroll
                for (int ni = 0; ni < 8; ni++)
                    mma_f16(acc[mi][ni], af[mi],
                            bq[ni >> 1][(ni & 1) * 2], bq[ni >> 1][(ni & 1) * 2 + 1]);
        }
    }

    const int g = lane >> 2, q = lane & 3;
    #pragma unroll
    for (int ni = 0; ni < 8; ni++) {
        int col = bcol + wn + ni * 8 + q * 2;
        float bb0 = bias[col], bb1 = bias[col + 1];
        #pragma unroll
        for (int mi = 0; mi < 4; mi++) {
            #pragma unroll
            for (int h = 0; h < 2; h++) {
                int row = brow + wm + mi * 16 + g + h * 8;
                size_t off = (size_t)row * N + col;
                float v0 = acc[mi][ni][h * 2 + 0] + bb0;
                float v1 = acc[mi][ni][h * 2 + 1] + bb1;
                if (DO_RES) {
                    __half2 rh = *(const __half2*)(res + off);
                    float2 rf2 = __half22float2(rh);
                    v0 += rf2.x; v1 += rf2.y;
                }
                if (DO_GELU) { v0 = gelu_exact(v0); v1 = gelu_exact(v1); }
                if (sizeof(OT) == 2) {
                    __half2 hv = __floats2half2_rn(v0, v1);
                    *(uint32_t*)((__half*)C + off) = *(uint32_t*)&hv;
                } else {
                    float2 o; o.x = v0; o.y = v1;
                    *(float2*)((float*)C + off) = o;
                }
            }
        }
    }
}

// ---------------- fp16 flash attention ----------------
// CTA per (b,t,h): 8 warps x 32 queries, keys in 64-chunks (double-buffered).
__global__ void __launch_bounds__(256) attn_mma(
    const __half* __restrict__ Q, const __half* __restrict__ KV, __half* __restrict__ O)
{
    extern __shared__ char asm_[];
    const uint32_t Qs = smem_u32(asm_) + AQ_B;
    const uint32_t Ps = smem_u32(asm_) + AP_B;
    const uint32_t Ks = smem_u32(asm_) + AK_B;
    const uint32_t Vs = smem_u32(asm_) + AV_B;

    const int idx = blockIdx.x;
    const int h = idx & 7;
    const int bt = idx >> 3;
    const int b = bt / T_;
    const int tid = threadIdx.x, warp = tid >> 5, lane = tid & 31;
    const int g = lane >> 2, q = lane & 3;
    const int wm = warp * 32;

    // Q: 256 rows x 8 granules, plain copy with swizzle
    {
        const __half* gq = Q + (size_t)(b * NF_) * E_ + h * DH_;
        #pragma unroll
        for (int i = tid; i < 256 * 8; i += 256) {
            int r = i >> 3, gg2 = i & 7;
            uint4 v = *(const uint4*)(gq + (size_t)r * E_ + gg2 * 8);
            *(uint4*)(asm_ + AQ_B + r * 128 + ((gg2 ^ (r & 7)) << 4)) = v;
        }
    }

    const __half* kvbase = KV + (size_t)bt * NF_ * 1024 + h * DH_;
    auto fillkv = [&](int ch) {
        int st = ch & 1;
        #pragma unroll
        for (int i = tid; i < 64 * 8; i += 256) {
            int r = i >> 3, gk = i & 7;
            const __half* src = kvbase + (size_t)(ch * 64 + r) * 1024 + gk * 8;
            uint32_t so = (uint32_t)(st * 8192 + r * 128 + ((gk ^ (r & 7)) << 4));
            cp16(Ks + so, src);
            cp16(Vs + so, src + 512);
        }
        asm volatile("cp.async.commit_group;" ::: "memory");
    };

    fillkv(0);

    float o[2][8][4];
    #pragma unroll
    for (int mi = 0; mi < 2; mi++)
        #pragma unroll
        for (int nd = 0; nd < 8; nd++)
            #pragma unroll
            for (int r = 0; r < 4; r++) o[mi][nd][r] = 0.0f;
    float mrow[2][2] = {{-1e30f, -1e30f}, {-1e30f, -1e30f}};
    float lrow[2][2] = {{0.0f, 0.0f}, {0.0f, 0.0f}};

    for (int ch = 0; ch < 4; ch++) {
        asm volatile("cp.async.wait_group 0;" ::: "memory");
        __syncthreads();
        if (ch + 1 < 4) fillkv(ch + 1);

        const uint32_t Kst = Ks + (ch & 1) * 8192;
        const uint32_t Vst = Vs + (ch & 1) * 8192;

        // ---- S = Q K^T (fp16 mma, k = d = 64) ----
        float s[2][8][4];
        #pragma unroll
        for (int mi = 0; mi < 2; mi++)
            #pragma unroll
            for (int ni = 0; ni < 8; ni++)
                #pragma unroll
                for (int r = 0; r < 4; r++) s[mi][ni][r] = 0.0f;

        #pragma unroll
        for (int ks = 0; ks < 4; ks++) {
            uint32_t af[2][4], bq[4][4];
            #pragma unroll
            for (int mi = 0; mi < 2; mi++) {
                int row = wm + mi * 16 + (lane & 15);
                uint32_t kg = (uint32_t)(ks * 2 + (lane >> 4));
                ldsm4(af[mi], Qs + (uint32_t)row * 128 + ((kg ^ (row & 7)) << 4));
            }
            #pragma unroll
            for (int nt = 0; nt < 4; nt++) {
                int nr = nt * 16 + ((lane >> 4) << 3) + (lane & 7);
                uint32_t kg = (uint32_t)(ks * 2 + ((lane >> 3) & 1));
                ldsm4(bq[nt], Kst + (uint32_t)nr * 128 + ((kg ^ (nr & 7)) << 4));
            }
            #pragma unroll
            for (int mi = 0; mi < 2; mi++)
                #pragma unroll
                for (int ni = 0; ni < 8; ni++)
                    mma_f16(s[mi][ni], af[mi],
                            bq[ni >> 1][(ni & 1) * 2], bq[ni >> 1][(ni & 1) * 2 + 1]);
        }

        // ---- online softmax (scale 1/8 folded here) ----
        #pragma unroll
        for (int mi = 0; mi < 2; mi++)
            #pragma unroll
            for (int ni = 0; ni < 8; ni++)
                #pragma unroll
                for (int r = 0; r < 4; r++) s[mi][ni][r] *= 0.125f;

        #pragma unroll
        for (int mi = 0; mi < 2; mi++) {
            #pragma unroll
            for (int hh = 0; hh < 2; hh++) {
                float rm = -1e30f;
                #pragma unroll
                for (int ni = 0; ni < 8; ni++)
                    rm = fmaxf(rm, fmaxf(s[mi][ni][hh * 2], s[mi][ni][hh * 2 + 1]));
                rm = fmaxf(rm, __shfl_xor_sync(0xffffffffu, rm, 1));
                rm = fmaxf(rm, __shfl_xor_sync(0xffffffffu, rm, 2));
                float mnew = fmaxf(mrow[mi][hh], rm);
                float alpha = __expf(mrow[mi][hh] - mnew);
                mrow[mi][hh] = mnew;
                float rs = 0.0f;
                #pragma unroll
                for (int ni = 0; ni < 8; ni++) {
                    float p0 = __expf(s[mi][ni][hh * 2]     - mnew);
                    float p1 = __expf(s[mi][ni][hh * 2 + 1] - mnew);
                    rs += p0 + p1;
                    s[mi][ni][hh * 2]     = p0;
                    s[mi][ni][hh * 2 + 1] = p1;
                }
                rs += __shfl_xor_sync(0xffffffffu, rs, 1);
                rs += __shfl_xor_sync(0xffffffffu, rs, 2);
                lrow[mi][hh] = lrow[mi][hh] * alpha + rs;
                #pragma unroll
                for (int nd = 0; nd < 8; nd++) {
                    o[mi][nd][hh * 2]     *= alpha;
                    o[mi][nd][hh * 2 + 1] *= alpha;
                }
            }
        }

        // ---- P -> smem (fp16), per-warp rows ----
        __syncwarp();
        #pragma unroll
        for (int mi = 0; mi < 2; mi++) {
            #pragma unroll
            for (int ni = 0; ni < 8; ni++) {
                int row = wm + mi * 16 + g;
                __half2 p01 = __floats2half2_rn(s[mi][ni][0], s[mi][ni][1]);
                __half2 p23 = __floats2half2_rn(s[mi][ni][2], s[mi][ni][3]);
                *(uint32_t*)(asm_ + AP_B + row * 128 + (((uint32_t)ni ^ (row & 7)) << 4) + q * 4)
                    = *(uint32_t*)&p01;
                int row2 = row + 8;
                *(uint32_t*)(asm_ + AP_B + row2 * 128 + (((uint32_t)ni ^ (row2 & 7)) << 4) + q * 4)
                    = *(uint32_t*)&p23;
            }
        }
        __syncwarp();

        // ---- O += P V (A = P row-major, B = V via ldmatrix.trans) ----
        #pragma unroll
        for (int ks = 0; ks < 4; ks++) {               // 16 keys per step
            uint32_t af[2][4], bv[4][4];
            #pragma unroll
            for (int mi = 0; mi < 2; mi++) {
                int row = wm + mi * 16 + (lane & 15);
                uint32_t kg = (uint32_t)(ks * 2 + (lane >> 4));
                ldsm4(af[mi], Ps + (uint32_t)row * 128 + ((kg ^ (row & 7)) << 4));
            }
            #pragma unroll
            for (int nt = 0; nt < 4; nt++) {           // d-tiles of 16
                int kr = ks * 16 + (lane & 7) + ((lane >> 3) & 1) * 8;
                uint32_t ng = (uint32_t)(nt * 2 + (lane >> 4));
                ldsm4t(bv[nt], Vst + (uint32_t)kr * 128 + ((ng ^ (kr & 7)) << 4));
            }
            #pragma unroll
            for (int mi = 0; mi < 2; mi++)
                #pragma unroll
                for (int nd = 0; nd < 8; nd++)
                    mma_f16(o[mi][nd], af[mi],
                            bv[nd >> 1][(nd & 1) * 2], bv[nd >> 1][(nd & 1) * 2 + 1]);
        }
        __syncwarp();
    }

    // ---- normalize + store fp16 ----
    #pragma unroll
    for (int mi = 0; mi < 2; mi++) {
        #pragma unroll
        for (int hh = 0; hh < 2; hh++) {
            float inv = 1.0f / lrow[mi][hh];
            int row = wm + mi * 16 + g + hh * 8;
            __half* orow = O + ((size_t)bt * NF_ + row) * E_ + h * DH_;
            #pragma unroll
            for (int nd = 0; nd < 8; nd++) {
                __half2 ov = __floats2half2_rn(o[mi][nd][hh * 2] * inv,
                                               o[mi][nd][hh * 2 + 1] * inv);
                *(uint32_t*)(orow + nd * 8 + 2 * q) = *(uint32_t*)&ov;
            }
        }
    }
}

// ---------------- host ----------------
extern "C" void kernel_launch(void* const* d_in, const int* in_sizes, int n_in,
                              void* d_out, int out_size)
{
    const float* inputs  = (const float*)d_in[0];
    const float* wq      = (const float*)d_in[1];
    const float* wk      = (const float*)d_in[2];
    const float* wv      = (const float*)d_in[3];
    const float* bq      = (const float*)d_in[4];
    const float* bk      = (const float*)d_in[5];
    const float* bv      = (const float*)d_in[6];
    const float* wo      = (const float*)d_in[7];
    const float* bo      = (const float*)d_in[8];
    const float* lnq_g   = (const float*)d_in[9];
    const float* lnq_b   = (const float*)d_in[10];
    const float* lnkv_g  = (const float*)d_in[11];
    const float* lnkv_b  = (const float*)d_in[12];
    const float* mlpq_w1 = (const float*)d_in[13];
    const float* mlpq_b1 = (const float*)d_in[14];
    const float* mlpq_w2 = (const float*)d_in[15];
    const float* mlpq_b2 = (const float*)d_in[16];
    const float* resln_g = (const float*)d_in[17];
    const float* resln_b = (const float*)d_in[18];
    const float* ln2_g   = (const float*)d_in[19];
    const float* ln2_b   = (const float*)d_in[20];
    const float* mlp_w1  = (const float*)d_in[21];
    const float* mlp_b1  = (const float*)d_in[22];
    const float* mlp_w2  = (const float*)d_in[23];
    const float* mlp_b2  = (const float*)d_in[24];
    float* out = (float*)d_out;

    __half *qln, *q, *kvln, *kv, *t1h, *t2h, *hid, *wtA, *wtB, *wqT;
    float *t1f, *bkvC;
    cudaGetSymbolAddress((void**)&qln,  g_qln);
    cudaGetSymbolAddress((void**)&q,    g_q);
    cudaGetSymbolAddress((void**)&kvln, g_kvln);
    cudaGetSymbolAddress((void**)&kv,   g_kv);
    cudaGetSymbolAddress((void**)&t1h,  g_t1h);
    cudaGetSymbolAddress((void**)&t2h,  g_t2h);
    cudaGetSymbolAddress((void**)&hid,  g_hid);
    cudaGetSymbolAddress((void**)&t1f,  g_t1f);
    cudaGetSymbolAddress((void**)&wtA,  g_wtA);
    cudaGetSymbolAddress((void**)&wtB,  g_wtB);
    cudaGetSymbolAddress((void**)&wqT,  g_wqT);
    cudaGetSymbolAddress((void**)&bkvC, g_bkv);

    __half* wkvT = wtA;                            // 1024 x 512
    __half* woT  = wtA + (size_t)2 * E_ * E_;
    __half* mq1T = wtB;                            // (M, E)
    __half* mq2T = wtB + (size_t)E_ * M_;          // (E, M)
    __half* m1T  = wtB + (size_t)2 * E_ * M_;      // (M, E)
    __half* m2T  = wtB + (size_t)3 * E_ * M_;      // (E, M)

    cudaFuncSetAttribute(hgemm<false,false,__half>, cudaFuncAttributeMaxDynamicSharedMemorySize, SMEM_TOTAL);
    cudaFuncSetAttribute(hgemm<true ,false,__half>, cudaFuncAttributeMaxDynamicSharedMemorySize, SMEM_TOTAL);
    cudaFuncSetAttribute(hgemm<false,true ,float >, cudaFuncAttributeMaxDynamicSharedMemorySize, SMEM_TOTAL);
    cudaFuncSetAttribute(hgemm<false,false,float >, cudaFuncAttributeMaxDynamicSharedMemorySize, SMEM_TOTAL);
    cudaFuncSetAttribute(attn_mma, cudaFuncAttributeMaxDynamicSharedMemorySize, ATTN_SMEM);

    TDesc td;
    int off = 0;
    auto seg = [&](int i, const float* W, __half* WT, int K, int N) {
        td.s[i].W = W; td.s[i].WT = WT; td.s[i].K = K; td.s[i].N = N; td.s[i].blk0 = off;
        off += (N / 32) * (K / 32);
    };
    seg(0, wk,      wkvT,                    E_, E_);
    seg(1, wv,      wkvT + (size_t)E_ * E_,  E_, E_);
    seg(2, wq,      wqT,                     E_, E_);
    seg(3, wo,      woT,                     E_, E_);
    seg(4, mlpq_w1, mq1T,                    E_, M_);
    seg(5, mlpq_w2, mq2T,                    M_, E_);
    seg(6, mlp_w1,  m1T,                     E_, M_);
    seg(7, mlp_w2,  m2T,                     M_, E_);
    td.bk = bk; td.bv = bv; td.bkv = bkvC;
    const int nblk_t = off;

    // 1) input LN -> fp16
    ln_in_kernel<<<B_ * HW_ * NF_, 128>>>(inputs, lnq_g, lnq_b, lnkv_g, lnkv_b, qln, kvln);
    // 2) weight transposes -> fp16 (+ bias concat), one launch
    transpose_all<<<nblk_t + 1, 256>>>(td, nblk_t);
    // 3) q projection
    hgemm<false,false,__half><<<dim3(E_/128, ROWS_Q/128), 128, SMEM_TOTAL>>>(qln, wqT, bq, nullptr, q, ROWS_Q, E_, E_);
    // 4) fused k|v projection (N=1024)   <-- ncu slot
    hgemm<false,false,__half><<<dim3(1024/128, ROWS_KV/128), 128, SMEM_TOTAL>>>(kvln, wkvT, bkvC, nullptr, kv, ROWS_KV, 1024, E_);
    // 5) attention -> t1h
    attn_mma<<<B_ * T_ * H_, 256, ATTN_SMEM>>>(q, kv, t1h);
    // 6) out projection -> t2h
    hgemm<false,false,__half><<<dim3(E_/128, ROWS_KV/128), 128, SMEM_TOTAL>>>(t1h, woT, bo, nullptr, t2h, ROWS_KV, E_, E_);
    // 7-8) mlp_q: t2h -> hid (GELU) -> t1f (+ residual kvln)
    hgemm<true ,false,__half><<<dim3(M_/128, ROWS_KV/128), 128, SMEM_TOTAL>>>(t2h, mq1T, mlpq_b1, nullptr, hid, ROWS_KV, M_, E_);
    hgemm<false,true ,float ><<<dim3(E_/128, ROWS_KV/128), 128, SMEM_TOTAL>>>(hid, mq2T, mlpq_b2, kvln,  t1f, ROWS_KV, E_, M_);
    // 9) res_ln + ln_2 fused: t1f -> t1h (fp16)
    dual_ln_kernel<<<ROWS_KV, 128>>>(t1f, resln_g, resln_b, ln2_g, ln2_b, t1h);
    // 10-11) final MLP: t1h -> hid (GELU) -> out (fp32)
    hgemm<true ,false,__half><<<dim3(M_/128, ROWS_KV/128), 128, SMEM_TOTAL>>>(t1h, m1T, mlp_b1, nullptr, hid, ROWS_KV, M_, E_);
    hgemm<false,false,float ><<<dim3(E_/128, ROWS_KV/128), 128, SMEM_TOTAL>>>(hid, m2T, mlp_b2, nullptr, out, ROWS_KV, E_, M_);
}

// round 11
// speedup vs baseline: 1.9498x; 1.5174x over previous
#include <cuda_runtime.h>
#include <cuda_fp16.h>
#include <math.h>
#include <stdint.h>

// Problem shapes
#define B_   8
#define HW_  32
#define T_   31
#define NF_  256
#define E_   512
#define M_   2048
#define H_   8
#define DH_  64

#define ROWS_Q   (B_ * NF_)            // 2048
#define ROWS_KV  (B_ * T_ * NF_)       // 63488

// hgemm tiling: CTA 128x128, K-chunk 64 (fp16), 3-stage, 4 warps of 64x64
#define TK 64
#define NSTAGE 3
#define STAGE_BYTES 32768
#define SMEM_TOTAL (NSTAGE * STAGE_BYTES)   // 98304

// Attention smem (bytes)
#define AQ_B 0
#define AP_B 32768
#define AK_B 65536
#define AV_B 81920
#define ATTN_SMEM 98304

// ---------------- static scratch ----------------
__device__ __half g_qln [ (size_t)ROWS_Q  * E_ ];
__device__ __half g_q   [ (size_t)ROWS_Q  * E_ ];
__device__ __half g_kvln[ (size_t)ROWS_KV * E_ ];
__device__ __half g_kv  [ (size_t)ROWS_KV * 1024 ];
__device__ __half g_t1h [ (size_t)ROWS_KV * E_ ];
__device__ __half g_t2h [ (size_t)ROWS_KV * E_ ];
__device__ __half g_hid [ (size_t)ROWS_KV * M_ ];
__device__ float  g_t1f [ (size_t)ROWS_KV * E_ ];
__device__ __half g_wtA [ (size_t)4 * E_ * E_ ];
__device__ __half g_wtB [ (size_t)4 * E_ * M_ ];
__device__ __half g_wqT [ (size_t)E_ * E_ ];
__device__ float  g_bkv [ 1024 ];

// ---------------- helpers ----------------
__device__ __forceinline__ float gelu_exact(float x) {
    return 0.5f * x * (1.0f + erff(x * 0.70710678118654752f));
}
__device__ __forceinline__ uint32_t smem_u32(const void* p) {
    uint32_t a;
    asm("{ .reg .u64 t; cvta.to.shared.u64 t, %1; cvt.u32.u64 %0, t; }" : "=r"(a) : "l"(p));
    return a;
}
__device__ __forceinline__ void cp16(uint32_t s, const void* g) {
    asm volatile("cp.async.cg.shared.global [%0], [%1], 16;" :: "r"(s), "l"(g));
}
__device__ __forceinline__ void ldsm4(uint32_t* r, uint32_t a) {
    asm volatile("ldmatrix.sync.aligned.m8n8.x4.shared.b16 {%0,%1,%2,%3}, [%4];"
        : "=r"(r[0]), "=r"(r[1]), "=r"(r[2]), "=r"(r[3]) : "r"(a));
}
__device__ __forceinline__ void ldsm4t(uint32_t* r, uint32_t a) {
    asm volatile("ldmatrix.sync.aligned.m8n8.x4.trans.shared.b16 {%0,%1,%2,%3}, [%4];"
        : "=r"(r[0]), "=r"(r[1]), "=r"(r[2]), "=r"(r[3]) : "r"(a));
}
__device__ __forceinline__ void mma_f16(float* d, const uint32_t* a, uint32_t b0, uint32_t b1) {
    asm volatile(
        "mma.sync.aligned.m16n8k16.row.col.f32.f16.f16.f32 "
        "{%0,%1,%2,%3}, {%4,%5,%6,%7}, {%8,%9}, {%0,%1,%2,%3};"
        : "+f"(d[0]), "+f"(d[1]), "+f"(d[2]), "+f"(d[3])
        : "r"(a[0]), "r"(a[1]), "r"(a[2]), "r"(a[3]), "r"(b0), "r"(b1));
}

__device__ __forceinline__ float blk_sum4(float v, float* sb) {   // 128 threads
    #pragma unroll
    for (int o = 16; o; o >>= 1) v += __shfl_xor_sync(0xffffffffu, v, o);
    if ((threadIdx.x & 31) == 0) sb[threadIdx.x >> 5] = v;
    __syncthreads();
    float r = sb[0] + sb[1] + sb[2] + sb[3];
    __syncthreads();
    return r;
}
__device__ __forceinline__ float blk_sum8(float v, float* sb) {   // 256 threads
    #pragma unroll
    for (int o = 16; o; o >>= 1) v += __shfl_xor_sync(0xffffffffu, v, o);
    if ((threadIdx.x & 31) == 0) sb[threadIdx.x >> 5] = v;
    __syncthreads();
    float r = sb[0] + sb[1] + sb[2] + sb[3] + sb[4] + sb[5] + sb[6] + sb[7];
    __syncthreads();
    return r;
}

// ---------------- fused pre-work: 8 weight transposes + bias concat + input LN ----------------
struct TSeg { const float* W; __half* WT; int K; int N; int blk0; };
struct PreDesc {
    TSeg s[8];
    const float *bk, *bv; float* bkvO;
    const float *X, *gq, *bq, *gkv, *bkvLN;
    __half *out_q, *out_kv;
};

__global__ void __launch_bounds__(256) pre_all(PreDesc d, int nblk_t)
{
    __shared__ float shm[32 * 33];
    int blk = blockIdx.x;

    if (blk < nblk_t) {                                  // --- transpose segment ---
        float (*t)[33] = (float(*)[33])shm;
        int si = 0;
        #pragma unroll
        for (int j = 1; j < 8; j++) if (blk >= d.s[j].blk0) si = j;
        const TSeg sg = d.s[si];
        int b = blk - sg.blk0;
        int nx = sg.N >> 5;
        int n0 = (b % nx) * 32, k0 = (b / nx) * 32;
        int tx = threadIdx.x & 31, ty = threadIdx.x >> 5;
        #pragma unroll
        for (int j = 0; j < 32; j += 8)
            t[ty + j][tx] = sg.W[(size_t)(k0 + ty + j) * sg.N + n0 + tx];
        __syncthreads();
        #pragma unroll
        for (int j = 0; j < 32; j += 8)
            sg.WT[(size_t)(n0 + ty + j) * sg.K + k0 + tx] = __float2half_rn(t[tx][ty + j]);
        return;
    }
    if (blk == nblk_t) {                                 // --- bias concat ---
        int i = threadIdx.x;
        #pragma unroll
        for (int j = 0; j < 4; j++) {
            int idx = i + j * 256;
            d.bkvO[idx] = (idx < 512) ? d.bk[idx] : d.bv[idx - 512];
        }
        return;
    }

    // --- input LN row (256 threads, float2 per thread) ---
    int r = blk - nblk_t - 1;                            // 0 .. 8191
    int b = r >> 13;
    int t = (r >> 8) & 31;
    int n = r & 255;
    int c = threadIdx.x * 2;

    float2 xv = *(const float2*)(d.X + (size_t)r * E_ + c);
    float s = xv.x + xv.y;
    float mean = blk_sum8(s, shm) * (1.0f / E_);
    float d0 = xv.x - mean, d1 = xv.y - mean;
    float var = blk_sum8(d0 * d0 + d1 * d1, shm) * (1.0f / E_);
    float rs = rsqrtf(var + 1e-6f);

    const float *g, *be; __half* dst;
    if (t == 0) { g = d.gq;  be = d.bq;    dst = d.out_q  + ((size_t)(b * NF_ + n)) * E_; }
    else        { g = d.gkv; be = d.bkvLN; dst = d.out_kv + ((size_t)((b * T_ + (t - 1)) * NF_ + n)) * E_; }

    float2 gg = *(const float2*)(g + c);
    float2 bb = *(const float2*)(be + c);
    __half2 h = __floats2half2_rn(d0 * rs * gg.x + bb.x, d1 * rs * gg.y + bb.y);
    *(uint32_t*)(dst + c) = *(uint32_t*)&h;
}

// ---------------- fused double LayerNorm: float in -> fp16 out ----------------
__global__ void __launch_bounds__(128) dual_ln_kernel(
    const float* __restrict__ X,
    const float* __restrict__ g1, const float* __restrict__ b1,
    const float* __restrict__ g2, const float* __restrict__ b2,
    __half* __restrict__ Y)
{
    __shared__ float sb[4];
    size_t r = blockIdx.x;
    int c = threadIdx.x * 4;
    float4 xv = *(const float4*)(X + r * E_ + c);

    float s = xv.x + xv.y + xv.z + xv.w;
    float mean = blk_sum4(s, sb) * (1.0f / E_);
    float d0 = xv.x - mean, d1 = xv.y - mean, d2 = xv.z - mean, d3 = xv.w - mean;
    float var = blk_sum4(d0*d0 + d1*d1 + d2*d2 + d3*d3, sb) * (1.0f / E_);
    float rs = rsqrtf(var + 1e-6f);

    float4 gg = *(const float4*)(g1 + c);
    float4 bb = *(const float4*)(b1 + c);
    float y0 = d0 * rs * gg.x + bb.x;
    float y1 = d1 * rs * gg.y + bb.y;
    float y2 = d2 * rs * gg.z + bb.z;
    float y3 = d3 * rs * gg.w + bb.w;

    float s2 = y0 + y1 + y2 + y3;
    float mean2 = blk_sum4(s2, sb) * (1.0f / E_);
    float e0 = y0 - mean2, e1 = y1 - mean2, e2 = y2 - mean2, e3 = y3 - mean2;
    float var2 = blk_sum4(e0*e0 + e1*e1 + e2*e2 + e3*e3, sb) * (1.0f / E_);
    float rs2 = rsqrtf(var2 + 1e-6f);

    float4 gg2 = *(const float4*)(g2 + c);
    float4 bb2 = *(const float4*)(b2 + c);
    __half2 h0 = __floats2half2_rn(e0 * rs2 * gg2.x + bb2.x, e1 * rs2 * gg2.y + bb2.y);
    __half2 h1 = __floats2half2_rn(e2 * rs2 * gg2.z + bb2.z, e3 * rs2 * gg2.w + bb2.w);
    uint2 u; u.x = *(uint32_t*)&h0; u.y = *(uint32_t*)&h1;
    *(uint2*)(Y + r * E_ + c) = u;
}

// ---------------- fp16 mma GEMM body (shared by hgemm / hgemm_dual) ----------------
template<bool DO_GELU, bool DO_RES, typename OT>
__device__ __forceinline__ void hgemm_body(
    const __half* __restrict__ A, const __half* __restrict__ BT,
    const float* __restrict__ bias, const __half* __restrict__ res,
    OT* __restrict__ C, int N, int K, int brow, int bcol, char* dsm)
{
    const uint32_t sb0 = smem_u32(dsm);
    const int tid = threadIdx.x, warp = tid >> 5, lane = tid & 31;
    const int wm = (warp >> 1) * 64, wn = (warp & 1) * 64;

    const int rf = tid >> 3, gf = tid & 7;
    const uint32_t fso = (uint32_t)rf * 128 + ((gf ^ (rf & 7)) << 4);
    const __half* gA = A  + (size_t)(brow + rf) * K + gf * 8;
    const __half* gB = BT + (size_t)(bcol + rf) * K + gf * 8;

    float acc[4][8][4];
    #pragma unroll
    for (int mi = 0; mi < 4; mi++)
        #pragma unroll
        for (int ni = 0; ni < 8; ni++)
            #pragma unroll
            for (int r = 0; r < 4; r++) acc[mi][ni][r] = 0.0f;

    const int nkt = K / TK;

    auto fill = [&](int kt) {
        const int st = kt % NSTAGE;
        uint32_t dA = sb0 + st * STAGE_BYTES;
        uint32_t dB = dA + 16384;
        const __half* ga = gA + kt * TK;
        const __half* gb = gB + kt * TK;
        #pragma unroll
        for (int i = 0; i < 8; i++) {
            uint32_t so = fso + (uint32_t)i * 2048;
            cp16(dA + so, ga + (size_t)i * 16 * K);
            cp16(dB + so, gb + (size_t)i * 16 * K);
        }
        asm volatile("cp.async.commit_group;" ::: "memory");
    };

    fill(0);
    if (nkt > 1) fill(1);

    for (int kt = 0; kt < nkt; kt++) {
        if (kt + 1 < nkt) asm volatile("cp.async.wait_group 1;" ::: "memory");
        else              asm volatile("cp.async.wait_group 0;" ::: "memory");
        __syncthreads();
        if (kt + 2 < nkt) fill(kt + 2);

        const int st = kt % NSTAGE;
        const uint32_t sA = sb0 + st * STAGE_BYTES;
        const uint32_t sB = sA + 16384;

        #pragma unroll
        for (int ks = 0; ks < 4; ks++) {
            uint32_t af[4][4], bq[4][4];
            #pragma unroll
            for (int mi = 0; mi < 4; mi++) {
                int row = wm + mi * 16 + (lane & 15);
                uint32_t kg = (uint32_t)(ks * 2 + (lane >> 4));
                ldsm4(af[mi], sA + (uint32_t)row * 128 + ((kg ^ (row & 7)) << 4));
            }
            #pragma unroll
            for (int nt = 0; nt < 4; nt++) {
                int nr = wn + nt * 16 + ((lane >> 4) << 3) + (lane & 7);
                uint32_t kg = (uint32_t)(ks * 2 + ((lane >> 3) & 1));
                ldsm4(bq[nt], sB + (uint32_t)nr * 128 + ((kg ^ (nr & 7)) << 4));
            }
            #pragma unroll
            for (int mi = 0; mi < 4; mi++)
                #pragma unroll
                for (int ni = 0; ni < 8; ni++)
                    mma_f16(acc[mi][ni], af[mi],
                            bq[ni >> 1][(ni & 1) * 2], bq[ni >> 1][(ni & 1) * 2 + 1]);
        }
    }

    const int g = lane >> 2, q = lane & 3;
    #pragma unroll
    for (int ni = 0; ni < 8; ni++) {
        int col = bcol + wn + ni * 8 + q * 2;
        float bb0 = bias[col], bb1 = bias[col + 1];
        #pragma unroll
        for (int mi = 0; mi < 4; mi++) {
            #pragma unroll
            for (int h = 0; h < 2; h++) {
                int row = brow + wm + mi * 16 + g + h * 8;
                size_t off = (size_t)row * N + col;
                float v0 = acc[mi][ni][h * 2 + 0] + bb0;
                float v1 = acc[mi][ni][h * 2 + 1] + bb1;
                if (DO_RES) {
                    __half2 rh = *(const __half2*)(res + off);
                    float2 rf2 = __half22float2(rh);
                    v0 += rf2.x; v1 += rf2.y;
                }
                if (DO_GELU) { v0 = gelu_exact(v0); v1 = gelu_exact(v1); }
                if (sizeof(OT) == 2) {
                    __half2 hv = __floats2half2_rn(v0, v1);
                    *(uint32_t*)((__half*)C + off) = *(uint32_t*)&hv;
                } else {
                    float2 o; o.x = v0; o.y = v1;
                    *(float2*)((float*)C + off) = o;
                }
            }
        }
    }
}

template<bool DO_GELU, bool DO_RES, typename OT>
__global__ void __launch_bounds__(128, 2) hgemm(
    const __half* __restrict__ A, const __half* __restrict__ BT,
    const float* __restrict__ bias, const __half* __restrict__ res,
    OT* __restrict__ C, int N, int K)
{
    extern __shared__ char dsm[];
    hgemm_body<DO_GELU, DO_RES, OT>(A, BT, bias, res, C, N, K,
                                    blockIdx.y * 128, blockIdx.x * 128, dsm);
}

// dual GEMM: flattened 1D grid covering two independent problems (kv-proj + q-proj)
struct DP {
    const __half *A1, *B1; const float* bias1; __half* C1; int N1, K1, ntiles1, nx1;
    const __half *A2, *B2; const float* bias2; __half* C2; int N2, K2, nx2;
};
__global__ void __launch_bounds__(128, 2) hgemm_dual(DP p)
{
    extern __shared__ char dsm[];
    int t = blockIdx.x;
    if (t < p.ntiles1) {
        hgemm_body<false, false, __half>(p.A1, p.B1, p.bias1, nullptr, p.C1, p.N1, p.K1,
                                         (t / p.nx1) << 7, (t % p.nx1) << 7, dsm);
    } else {
        t -= p.ntiles1;
        hgemm_body<false, false, __half>(p.A2, p.B2, p.bias2, nullptr, p.C2, p.N2, p.K2,
                                         (t / p.nx2) << 7, (t % p.nx2) << 7, dsm);
    }
}

// ---------------- fp16 flash attention (Q pre-scaled by 1/8 at fill — exact) ----------------
__global__ void __launch_bounds__(256) attn_mma(
    const __half* __restrict__ Q, const __half* __restrict__ KV, __half* __restrict__ O)
{
    extern __shared__ char asm_[];
    const uint32_t Qs = smem_u32(asm_) + AQ_B;
    const uint32_t Ps = smem_u32(asm_) + AP_B;
    const uint32_t Ks = smem_u32(asm_) + AK_B;
    const uint32_t Vs = smem_u32(asm_) + AV_B;

    const int idx = blockIdx.x;
    const int h = idx & 7;
    const int bt = idx >> 3;
    const int b = bt / T_;
    const int tid = threadIdx.x, warp = tid >> 5, lane = tid & 31;
    const int g = lane >> 2, q = lane & 3;
    const int wm = warp * 32;

    {
        const __half* gq = Q + (size_t)(b * NF_) * E_ + h * DH_;
        const __half2 sc = __half2half2(__float2half(0.125f));   // exact 2^-3
        #pragma unroll
        for (int i = tid; i < 256 * 8; i += 256) {
            int r = i >> 3, gg2 = i & 7;
            uint4 v = *(const uint4*)(gq + (size_t)r * E_ + gg2 * 8);
            __half2* hv = (__half2*)&v;
            #pragma unroll
            for (int j = 0; j < 4; j++) hv[j] = __hmul2(hv[j], sc);
            *(uint4*)(asm_ + AQ_B + r * 128 + ((gg2 ^ (r & 7)) << 4)) = v;
        }
    }

    const __half* kvbase = KV + (size_t)bt * NF_ * 1024 + h * DH_;
    auto fillkv = [&](int ch) {
        int st = ch & 1;
        #pragma unroll
        for (int i = tid; i < 64 * 8; i += 256) {
            int r = i >> 3, gk = i & 7;
            const __half* src = kvbase + (size_t)(ch * 64 + r) * 1024 + gk * 8;
            uint32_t so = (uint32_t)(st * 8192 + r * 128 + ((gk ^ (r & 7)) << 4));
            cp16(Ks + so, src);
            cp16(Vs + so, src + 512);
        }
        asm volatile("cp.async.commit_group;" ::: "memory");
    };

    fillkv(0);

    float o[2][8][4];
    #pragma unroll
    for (int mi = 0; mi < 2; mi++)
        #pragma unroll
        for (int nd = 0; nd < 8; nd++)
            #pragma unroll
            for (int r = 0; r < 4; r++) o[mi][nd][r] = 0.0f;
    float mrow[2][2] = {{-1e30f, -1e30f}, {-1e30f, -1e30f}};
    float lrow[2][2] = {{0.0f, 0.0f}, {0.0f, 0.0f}};

    for (int ch = 0; ch < 4; ch++) {
        asm volatile("cp.async.wait_group 0;" ::: "memory");
        __syncthreads();
        if (ch + 1 < 4) fillkv(ch + 1);

        const uint32_t Kst = Ks + (ch & 1) * 8192;
        const uint32_t Vst = Vs + (ch & 1) * 8192;

        float s[2][8][4];
        #pragma unroll
        for (int mi = 0; mi < 2; mi++)
            #pragma unroll
            for (int ni = 0; ni < 8; ni++)
                #pragma unroll
                for (int r = 0; r < 4; r++) s[mi][ni][r] = 0.0f;

        #pragma unroll
        for (int ks = 0; ks < 4; ks++) {
            uint32_t af[2][4], bq[4][4];
            #pragma unroll
            for (int mi = 0; mi < 2; mi++) {
                int row = wm + mi * 16 + (lane & 15);
                uint32_t kg = (uint32_t)(ks * 2 + (lane >> 4));
                ldsm4(af[mi], Qs + (uint32_t)row * 128 + ((kg ^ (row & 7)) << 4));
            }
            #pragma unroll
            for (int nt = 0; nt < 4; nt++) {
                int nr = nt * 16 + ((lane >> 4) << 3) + (lane & 7);
                uint32_t kg = (uint32_t)(ks * 2 + ((lane >> 3) & 1));
                ldsm4(bq[nt], Kst + (uint32_t)nr * 128 + ((kg ^ (nr & 7)) << 4));
            }
            #pragma unroll
            for (int mi = 0; mi < 2; mi++)
                #pragma unroll
                for (int ni = 0; ni < 8; ni++)
                    mma_f16(s[mi][ni], af[mi],
                            bq[ni >> 1][(ni & 1) * 2], bq[ni >> 1][(ni & 1) * 2 + 1]);
        }

        #pragma unroll
        for (int mi = 0; mi < 2; mi++) {
            #pragma unroll
            for (int hh = 0; hh < 2; hh++) {
                float rm = -1e30f;
                #pragma unroll
                for (int ni = 0; ni < 8; ni++)
                    rm = fmaxf(rm, fmaxf(s[mi][ni][hh * 2], s[mi][ni][hh * 2 + 1]));
                rm = fmaxf(rm, __shfl_xor_sync(0xffffffffu, rm, 1));
                rm = fmaxf(rm, __shfl_xor_sync(0xffffffffu, rm, 2));
                float mnew = fmaxf(mrow[mi][hh], rm);
                float alpha = __expf(mrow[mi][hh] - mnew);
                mrow[mi][hh] = mnew;
                float rs = 0.0f;
                #pragma unroll
                for (int ni = 0; ni < 8; ni++) {
                    float p0 = __expf(s[mi][ni][hh * 2]     - mnew);
                    float p1 = __expf(s[mi][ni][hh * 2 + 1] - mnew);
                    rs += p0 + p1;
                    s[mi][ni][hh * 2]     = p0;
                    s[mi][ni][hh * 2 + 1] = p1;
                }
                rs += __shfl_xor_sync(0xffffffffu, rs, 1);
                rs += __shfl_xor_sync(0xffffffffu, rs, 2);
                lrow[mi][hh] = lrow[mi][hh] * alpha + rs;
                #pragma unroll
                for (int nd = 0; nd < 8; nd++) {
                    o[mi][nd][hh * 2]     *= alpha;
                    o[mi][nd][hh * 2 + 1] *= alpha;
                }
            }
        }

        __syncwarp();
        #pragma unroll
        for (int mi = 0; mi < 2; mi++) {
            #pragma unroll
            for (int ni = 0; ni < 8; ni++) {
                int row = wm + mi * 16 + g;
                __half2 p01 = __floats2half2_rn(s[mi][ni][0], s[mi][ni][1]);
                __half2 p23 = __floats2half2_rn(s[mi][ni][2], s[mi][ni][3]);
                *(uint32_t*)(asm_ + AP_B + row * 128 + (((uint32_t)ni ^ (row & 7)) << 4) + q * 4)
                    = *(uint32_t*)&p01;
                int row2 = row + 8;
                *(uint32_t*)(asm_ + AP_B + row2 * 128 + (((uint32_t)ni ^ (row2 & 7)) << 4) + q * 4)
                    = *(uint32_t*)&p23;
            }
        }
        __syncwarp();

        #pragma unroll
        for (int ks = 0; ks < 4; ks++) {
            uint32_t af[2][4], bv[4][4];
            #pragma unroll
            for (int mi = 0; mi < 2; mi++) {
                int row = wm + mi * 16 + (lane & 15);
                uint32_t kg = (uint32_t)(ks * 2 + (lane >> 4));
                ldsm4(af[mi], Ps + (uint32_t)row * 128 + ((kg ^ (row & 7)) << 4));
            }
            #pragma unroll
            for (int nt = 0; nt < 4; nt++) {
                int kr = ks * 16 + (lane & 7) + ((lane >> 3) & 1) * 8;
                uint32_t ng = (uint32_t)(nt * 2 + (lane >> 4));
                ldsm4t(bv[nt], Vst + (uint32_t)kr * 128 + ((ng ^ (kr & 7)) << 4));
            }
            #pragma unroll
            for (int mi = 0; mi < 2; mi++)
                #pragma unroll
                for (int nd = 0; nd < 8; nd++)
                    mma_f16(o[mi][nd], af[mi],
                            bv[nd >> 1][(nd & 1) * 2], bv[nd >> 1][(nd & 1) * 2 + 1]);
        }
        __syncwarp();
    }

    #pragma unroll
    for (int mi = 0; mi < 2; mi++) {
        #pragma unroll
        for (int hh = 0; hh < 2; hh++) {
            float inv = 1.0f / lrow[mi][hh];
            int row = wm + mi * 16 + g + hh * 8;
            __half* orow = O + ((size_t)bt * NF_ + row) * E_ + h * DH_;
            #pragma unroll
            for (int nd = 0; nd < 8; nd++) {
                __half2 ov = __floats2half2_rn(o[mi][nd][hh * 2] * inv,
                                               o[mi][nd][hh * 2 + 1] * inv);
                *(uint32_t*)(orow + nd * 8 + 2 * q) = *(uint32_t*)&ov;
            }
        }
    }
}

// ---------------- host ----------------
extern "C" void kernel_launch(void* const* d_in, const int* in_sizes, int n_in,
                              void* d_out, int out_size)
{
    const float* inputs  = (const float*)d_in[0];
    const float* wq      = (const float*)d_in[1];
    const float* wk      = (const float*)d_in[2];
    const float* wv      = (const float*)d_in[3];
    const float* bq      = (const float*)d_in[4];
    const float* bk      = (const float*)d_in[5];
    const float* bv      = (const float*)d_in[6];
    const float* wo      = (const float*)d_in[7];
    const float* bo      = (const float*)d_in[8];
    const float* lnq_g   = (const float*)d_in[9];
    const float* lnq_b   = (const float*)d_in[10];
    const float* lnkv_g  = (const float*)d_in[11];
    const float* lnkv_b  = (const float*)d_in[12];
    const float* mlpq_w1 = (const float*)d_in[13];
    const float* mlpq_b1 = (const float*)d_in[14];
    const float* mlpq_w2 = (const float*)d_in[15];
    const float* mlpq_b2 = (const float*)d_in[16];
    const float* resln_g = (const float*)d_in[17];
    const float* resln_b = (const float*)d_in[18];
    const float* ln2_g   = (const float*)d_in[19];
    const float* ln2_b   = (const float*)d_in[20];
    const float* mlp_w1  = (const float*)d_in[21];
    const float* mlp_b1  = (const float*)d_in[22];
    const float* mlp_w2  = (const float*)d_in[23];
    const float* mlp_b2  = (const float*)d_in[24];
    float* out = (float*)d_out;

    __half *qln, *q, *kvln, *kv, *t1h, *t2h, *hid, *wtA, *wtB, *wqT;
    float *t1f, *bkvC;
    cudaGetSymbolAddress((void**)&qln,  g_qln);
    cudaGetSymbolAddress((void**)&q,    g_q);
    cudaGetSymbolAddress((void**)&kvln, g_kvln);
    cudaGetSymbolAddress((void**)&kv,   g_kv);
    cudaGetSymbolAddress((void**)&t1h,  g_t1h);
    cudaGetSymbolAddress((void**)&t2h,  g_t2h);
    cudaGetSymbolAddress((void**)&hid,  g_hid);
    cudaGetSymbolAddress((void**)&t1f,  g_t1f);
    cudaGetSymbolAddress((void**)&wtA,  g_wtA);
    cudaGetSymbolAddress((void**)&wtB,  g_wtB);
    cudaGetSymbolAddress((void**)&wqT,  g_wqT);
    cudaGetSymbolAddress((void**)&bkvC, g_bkv);

    __half* wkvT = wtA;
    __half* woT  = wtA + (size_t)2 * E_ * E_;
    __half* mq1T = wtB;
    __half* mq2T = wtB + (size_t)E_ * M_;
    __half* m1T  = wtB + (size_t)2 * E_ * M_;
    __half* m2T  = wtB + (size_t)3 * E_ * M_;

    cudaFuncSetAttribute(hgemm<false,false,__half>, cudaFuncAttributeMaxDynamicSharedMemorySize, SMEM_TOTAL);
    cudaFuncSetAttribute(hgemm<true ,false,__half>, cudaFuncAttributeMaxDynamicSharedMemorySize, SMEM_TOTAL);
    cudaFuncSetAttribute(hgemm<false,true ,float >, cudaFuncAttributeMaxDynamicSharedMemorySize, SMEM_TOTAL);
    cudaFuncSetAttribute(hgemm<false,false,float >, cudaFuncAttributeMaxDynamicSharedMemorySize, SMEM_TOTAL);
    cudaFuncSetAttribute(hgemm_dual, cudaFuncAttributeMaxDynamicSharedMemorySize, SMEM_TOTAL);
    cudaFuncSetAttribute(attn_mma, cudaFuncAttributeMaxDynamicSharedMemorySize, ATTN_SMEM);

    PreDesc pd;
    int off = 0;
    auto seg = [&](int i, const float* W, __half* WT, int K, int N) {
        pd.s[i].W = W; pd.s[i].WT = WT; pd.s[i].K = K; pd.s[i].N = N; pd.s[i].blk0 = off;
        off += (N / 32) * (K / 32);
    };
    seg(0, wk,      wkvT,                    E_, E_);
    seg(1, wv,      wkvT + (size_t)E_ * E_,  E_, E_);
    seg(2, wq,      wqT,                     E_, E_);
    seg(3, wo,      woT,                     E_, E_);
    seg(4, mlpq_w1, mq1T,                    E_, M_);
    seg(5, mlpq_w2, mq2T,                    M_, E_);
    seg(6, mlp_w1,  m1T,                     E_, M_);
    seg(7, mlp_w2,  m2T,                     M_, E_);
    pd.bk = bk; pd.bv = bv; pd.bkvO = bkvC;
    pd.X = inputs; pd.gq = lnq_g; pd.bq = lnq_b; pd.gkv = lnkv_g; pd.bkvLN = lnkv_b;
    pd.out_q = qln; pd.out_kv = kvln;
    const int nblk_t = off;                         // 5120

    DP dp;
    dp.A1 = kvln; dp.B1 = wkvT; dp.bias1 = bkvC; dp.C1 = kv;
    dp.N1 = 1024; dp.K1 = E_; dp.nx1 = 1024 / 128;
    dp.ntiles1 = (ROWS_KV / 128) * dp.nx1;          // 3968
    dp.A2 = qln; dp.B2 = wqT; dp.bias2 = bq; dp.C2 = q;
    dp.N2 = E_; dp.K2 = E_; dp.nx2 = E_ / 128;
    const int ntiles2 = (ROWS_Q / 128) * dp.nx2;    // 16

    // 1) fused pre-work: transposes + bias concat + input LN (one launch)
    pre_all<<<nblk_t + 1 + B_ * HW_ * NF_, 256>>>(pd, nblk_t);
    // 2) kv projection + q projection in one launch
    hgemm_dual<<<dp.ntiles1 + ntiles2, 128, SMEM_TOTAL>>>(dp);
    // 3) attention -> t1h
    attn_mma<<<B_ * T_ * H_, 256, ATTN_SMEM>>>(q, kv, t1h);
    // 4) out projection -> t2h
    hgemm<false,false,__half><<<dim3(E_/128, ROWS_KV/128), 128, SMEM_TOTAL>>>(t1h, woT, bo, nullptr, t2h, E_, E_);
    // 5-6) mlp_q: t2h -> hid (GELU) -> t1f (+ residual kvln)
    hgemm<true ,false,__half><<<dim3(M_/128, ROWS_KV/128), 128, SMEM_TOTAL>>>(t2h, mq1T, mlpq_b1, nullptr, hid, M_, E_);
    hgemm<false,true ,float ><<<dim3(E_/128, ROWS_KV/128), 128, SMEM_TOTAL>>>(hid, mq2T, mlpq_b2, kvln,  t1f, E_, M_);
    // 7) res_ln + ln_2 fused: t1f -> t1h
    dual_ln_kernel<<<ROWS_KV, 128>>>(t1f, resln_g, resln_b, ln2_g, ln2_b, t1h);
    // 8-9) final MLP: t1h -> hid (GELU) -> out (fp32)
    hgemm<true ,false,__half><<<dim3(M_/128, ROWS_KV/128), 128, SMEM_TOTAL>>>(t1h, m1T, mlp_b1, nullptr, hid, M_, E_);
    hgemm<false,false,float ><<<dim3(E_/128, ROWS_KV/128), 128, SMEM_TOTAL>>>(hid, m2T, mlp_b2, nullptr, out, E_, M_);
}

// round 12
// speedup vs baseline: 1.9631x; 1.0068x over previous
#include <cuda_runtime.h>
#include <cuda_fp16.h>
#include <math.h>
#include <stdint.h>

// Problem shapes
#define B_   8
#define HW_  32
#define T_   31
#define NF_  256
#define E_   512
#define M_   2048
#define H_   8
#define DH_  64

#define ROWS_Q   (B_ * NF_)            // 2048
#define ROWS_KV  (B_ * T_ * NF_)       // 63488

// hgemm tiling: CTA 128x128, K-chunk 64 (fp16), 3-stage, 4 warps of 64x64
#define TK 64
#define NSTAGE 3
#define STAGE_BYTES 32768
#define SMEM_TOTAL (NSTAGE * STAGE_BYTES)   // 98304

// Attention smem (bytes)
#define AQ_B 0
#define AP_B 32768
#define AK_B 65536
#define AV_B 81920
#define ATTN_SMEM 98304

// ---------------- static scratch ----------------
__device__ __half g_qln [ (size_t)ROWS_Q  * E_ ];
__device__ __half g_q   [ (size_t)ROWS_Q  * E_ ];
__device__ __half g_kvln[ (size_t)ROWS_KV * E_ ];
__device__ __half g_kv  [ (size_t)ROWS_KV * 1024 ];
__device__ __half g_t1h [ (size_t)ROWS_KV * E_ ];
__device__ __half g_t2h [ (size_t)ROWS_KV * E_ ];
__device__ __half g_hid [ (size_t)ROWS_KV * M_ ];
__device__ __half g_wtA [ (size_t)4 * E_ * E_ ];
__device__ __half g_wtB [ (size_t)4 * E_ * M_ ];
__device__ __half g_wqT [ (size_t)E_ * E_ ];
__device__ float  g_bkv [ 1024 ];

// ---------------- helpers ----------------
__device__ __forceinline__ float gelu_exact(float x) {
    return 0.5f * x * (1.0f + erff(x * 0.70710678118654752f));
}
__device__ __forceinline__ uint32_t smem_u32(const void* p) {
    uint32_t a;
    asm("{ .reg .u64 t; cvta.to.shared.u64 t, %1; cvt.u32.u64 %0, t; }" : "=r"(a) : "l"(p));
    return a;
}
__device__ __forceinline__ void cp16(uint32_t s, const void* g) {
    asm volatile("cp.async.cg.shared.global [%0], [%1], 16;" :: "r"(s), "l"(g));
}
__device__ __forceinline__ void ldsm4(uint32_t* r, uint32_t a) {
    asm volatile("ldmatrix.sync.aligned.m8n8.x4.shared.b16 {%0,%1,%2,%3}, [%4];"
        : "=r"(r[0]), "=r"(r[1]), "=r"(r[2]), "=r"(r[3]) : "r"(a));
}
__device__ __forceinline__ void ldsm4t(uint32_t* r, uint32_t a) {
    asm volatile("ldmatrix.sync.aligned.m8n8.x4.trans.shared.b16 {%0,%1,%2,%3}, [%4];"
        : "=r"(r[0]), "=r"(r[1]), "=r"(r[2]), "=r"(r[3]) : "r"(a));
}
__device__ __forceinline__ void mma_f16(float* d, const uint32_t* a, uint32_t b0, uint32_t b1) {
    asm volatile(
        "mma.sync.aligned.m16n8k16.row.col.f32.f16.f16.f32 "
        "{%0,%1,%2,%3}, {%4,%5,%6,%7}, {%8,%9}, {%0,%1,%2,%3};"
        : "+f"(d[0]), "+f"(d[1]), "+f"(d[2]), "+f"(d[3])
        : "r"(a[0]), "r"(a[1]), "r"(a[2]), "r"(a[3]), "r"(b0), "r"(b1));
}

__device__ __forceinline__ float blk_sum4(float v, float* sb) {   // 128 threads
    #pragma unroll
    for (int o = 16; o; o >>= 1) v += __shfl_xor_sync(0xffffffffu, v, o);
    if ((threadIdx.x & 31) == 0) sb[threadIdx.x >> 5] = v;
    __syncthreads();
    float r = sb[0] + sb[1] + sb[2] + sb[3];
    __syncthreads();
    return r;
}
__device__ __forceinline__ float blk_sum8(float v, float* sb) {   // 256 threads
    #pragma unroll
    for (int o = 16; o; o >>= 1) v += __shfl_xor_sync(0xffffffffu, v, o);
    if ((threadIdx.x & 31) == 0) sb[threadIdx.x >> 5] = v;
    __syncthreads();
    float r = sb[0] + sb[1] + sb[2] + sb[3] + sb[4] + sb[5] + sb[6] + sb[7];
    __syncthreads();
    return r;
}

// ---------------- fused pre-work: 8 weight transposes + bias concat + input LN ----------------
struct TSeg { const float* W; __half* WT; int K; int N; int blk0; };
struct PreDesc {
    TSeg s[8];
    const float *bk, *bv; float* bkvO;
    const float *X, *gq, *bq, *gkv, *bkvLN;
    __half *out_q, *out_kv;
};

__global__ void __launch_bounds__(256) pre_all(PreDesc d, int nblk_t)
{
    __shared__ float shm[32 * 33];
    int blk = blockIdx.x;

    if (blk < nblk_t) {                                  // --- transpose segment ---
        float (*t)[33] = (float(*)[33])shm;
        int si = 0;
        #pragma unroll
        for (int j = 1; j < 8; j++) if (blk >= d.s[j].blk0) si = j;
        const TSeg sg = d.s[si];
        int b = blk - sg.blk0;
        int nx = sg.N >> 5;
        int n0 = (b % nx) * 32, k0 = (b / nx) * 32;
        int tx = threadIdx.x & 31, ty = threadIdx.x >> 5;
        #pragma unroll
        for (int j = 0; j < 32; j += 8)
            t[ty + j][tx] = sg.W[(size_t)(k0 + ty + j) * sg.N + n0 + tx];
        __syncthreads();
        #pragma unroll
        for (int j = 0; j < 32; j += 8)
            sg.WT[(size_t)(n0 + ty + j) * sg.K + k0 + tx] = __float2half_rn(t[tx][ty + j]);
        return;
    }
    if (blk == nblk_t) {                                 // --- bias concat ---
        int i = threadIdx.x;
        #pragma unroll
        for (int j = 0; j < 4; j++) {
            int idx = i + j * 256;
            d.bkvO[idx] = (idx < 512) ? d.bk[idx] : d.bv[idx - 512];
        }
        return;
    }

    // --- input LN row (256 threads, float2 per thread) ---
    int r = blk - nblk_t - 1;                            // 0 .. 8191
    int b = r >> 13;
    int t = (r >> 8) & 31;
    int n = r & 255;
    int c = threadIdx.x * 2;

    float2 xv = *(const float2*)(d.X + (size_t)r * E_ + c);
    float s = xv.x + xv.y;
    float mean = blk_sum8(s, shm) * (1.0f / E_);
    float d0 = xv.x - mean, d1 = xv.y - mean;
    float var = blk_sum8(d0 * d0 + d1 * d1, shm) * (1.0f / E_);
    float rs = rsqrtf(var + 1e-6f);

    const float *g, *be; __half* dst;
    if (t == 0) { g = d.gq;  be = d.bq;    dst = d.out_q  + ((size_t)(b * NF_ + n)) * E_; }
    else        { g = d.gkv; be = d.bkvLN; dst = d.out_kv + ((size_t)((b * T_ + (t - 1)) * NF_ + n)) * E_; }

    float2 gg = *(const float2*)(g + c);
    float2 bb = *(const float2*)(be + c);
    __half2 h = __floats2half2_rn(d0 * rs * gg.x + bb.x, d1 * rs * gg.y + bb.y);
    *(uint32_t*)(dst + c) = *(uint32_t*)&h;
}

// ---------------- fused double LayerNorm: fp16 in -> fp16 out ----------------
__global__ void __launch_bounds__(128) dual_ln_kernel(
    const __half* __restrict__ X,
    const float* __restrict__ g1, const float* __restrict__ b1,
    const float* __restrict__ g2, const float* __restrict__ b2,
    __half* __restrict__ Y)
{
    __shared__ float sb[4];
    size_t r = blockIdx.x;
    int c = threadIdx.x * 4;
    uint2 xu = *(const uint2*)(X + r * E_ + c);
    float2 xa = __half22float2(*(__half2*)&xu.x);
    float2 xb = __half22float2(*(__half2*)&xu.y);

    float s = xa.x + xa.y + xb.x + xb.y;
    float mean = blk_sum4(s, sb) * (1.0f / E_);
    float d0 = xa.x - mean, d1 = xa.y - mean, d2 = xb.x - mean, d3 = xb.y - mean;
    float var = blk_sum4(d0*d0 + d1*d1 + d2*d2 + d3*d3, sb) * (1.0f / E_);
    float rs = rsqrtf(var + 1e-6f);

    float4 gg = *(const float4*)(g1 + c);
    float4 bb = *(const float4*)(b1 + c);
    float y0 = d0 * rs * gg.x + bb.x;
    float y1 = d1 * rs * gg.y + bb.y;
    float y2 = d2 * rs * gg.z + bb.z;
    float y3 = d3 * rs * gg.w + bb.w;

    float s2 = y0 + y1 + y2 + y3;
    float mean2 = blk_sum4(s2, sb) * (1.0f / E_);
    float e0 = y0 - mean2, e1 = y1 - mean2, e2 = y2 - mean2, e3 = y3 - mean2;
    float var2 = blk_sum4(e0*e0 + e1*e1 + e2*e2 + e3*e3, sb) * (1.0f / E_);
    float rs2 = rsqrtf(var2 + 1e-6f);

    float4 gg2 = *(const float4*)(g2 + c);
    float4 bb2 = *(const float4*)(b2 + c);
    __half2 h0 = __floats2half2_rn(e0 * rs2 * gg2.x + bb2.x, e1 * rs2 * gg2.y + bb2.y);
    __half2 h1 = __floats2half2_rn(e2 * rs2 * gg2.z + bb2.z, e3 * rs2 * gg2.w + bb2.w);
    uint2 u; u.x = *(uint32_t*)&h0; u.y = *(uint32_t*)&h1;
    *(uint2*)(Y + r * E_ + c) = u;
}

// ---------------- fp16 mma GEMM body ----------------
template<bool DO_GELU, bool DO_RES, typename OT>
__device__ __forceinline__ void hgemm_body(
    const __half* __restrict__ A, const __half* __restrict__ BT,
    const float* __restrict__ bias, const __half* __restrict__ res,
    OT* __restrict__ C, int N, int K, int brow, int bcol, char* dsm)
{
    const uint32_t sb0 = smem_u32(dsm);
    const int tid = threadIdx.x, warp = tid >> 5, lane = tid & 31;
    const int wm = (warp >> 1) * 64, wn = (warp & 1) * 64;

    const int rf = tid >> 3, gf = tid & 7;
    const uint32_t fso = (uint32_t)rf * 128 + ((gf ^ (rf & 7)) << 4);
    const __half* gA = A  + (size_t)(brow + rf) * K + gf * 8;
    const __half* gB = BT + (size_t)(bcol + rf) * K + gf * 8;

    float acc[4][8][4];
    #pragma unroll
    for (int mi = 0; mi < 4; mi++)
        #pragma unroll
        for (int ni = 0; ni < 8; ni++)
            #pragma unroll
            for (int r = 0; r < 4; r++) acc[mi][ni][r] = 0.0f;

    const int nkt = K / TK;

    auto fill = [&](int kt) {
        const int st = kt % NSTAGE;
        uint32_t dA = sb0 + st * STAGE_BYTES;
        uint32_t dB = dA + 16384;
        const __half* ga = gA + kt * TK;
        const __half* gb = gB + kt * TK;
        #pragma unroll
        for (int i = 0; i < 8; i++) {
            uint32_t so = fso + (uint32_t)i * 2048;
            cp16(dA + so, ga + (size_t)i * 16 * K);
            cp16(dB + so, gb + (size_t)i * 16 * K);
        }
        asm volatile("cp.async.commit_group;" ::: "memory");
    };

    fill(0);
    if (nkt > 1) fill(1);

    for (int kt = 0; kt < nkt; kt++) {
        if (kt + 1 < nkt) asm volatile("cp.async.wait_group 1;" ::: "memory");
        else              asm volatile("cp.async.wait_group 0;" ::: "memory");
        __syncthreads();
        if (kt + 2 < nkt) fill(kt + 2);

        const int st = kt % NSTAGE;
        const uint32_t sA = sb0 + st * STAGE_BYTES;
        const uint32_t sB = sA + 16384;

        #pragma unroll
        for (int ks = 0; ks < 4; ks++) {
            uint32_t af[4][4], bq[4][4];
            #pragma unroll
            for (int mi = 0; mi < 4; mi++) {
                int row = wm + mi * 16 + (lane & 15);
                uint32_t kg = (uint32_t)(ks * 2 + (lane >> 4));
                ldsm4(af[mi], sA + (uint32_t)row * 128 + ((kg ^ (row & 7)) << 4));
            }
            #pragma unroll
            for (int nt = 0; nt < 4; nt++) {
                int nr = wn + nt * 16 + ((lane >> 4) << 3) + (lane & 7);
                uint32_t kg = (uint32_t)(ks * 2 + ((lane >> 3) & 1));
                ldsm4(bq[nt], sB + (uint32_t)nr * 128 + ((kg ^ (nr & 7)) << 4));
            }
            #pragma unroll
            for (int mi = 0; mi < 4; mi++)
                #pragma unroll
                for (int ni = 0; ni < 8; ni++)
                    mma_f16(acc[mi][ni], af[mi],
                            bq[ni >> 1][(ni & 1) * 2], bq[ni >> 1][(ni & 1) * 2 + 1]);
        }
    }

    const int g = lane >> 2, q = lane & 3;
    #pragma unroll
    for (int ni = 0; ni < 8; ni++) {
        int col = bcol + wn + ni * 8 + q * 2;
        float bb0 = bias[col], bb1 = bias[col + 1];
        #pragma unroll
        for (int mi = 0; mi < 4; mi++) {
            #pragma unroll
            for (int h = 0; h < 2; h++) {
                int row = brow + wm + mi * 16 + g + h * 8;
                size_t off = (size_t)row * N + col;
                float v0 = acc[mi][ni][h * 2 + 0] + bb0;
                float v1 = acc[mi][ni][h * 2 + 1] + bb1;
                if (DO_RES) {
                    __half2 rh = *(const __half2*)(res + off);
                    float2 rf2 = __half22float2(rh);
                    v0 += rf2.x; v1 += rf2.y;
                }
                if (DO_GELU) { v0 = gelu_exact(v0); v1 = gelu_exact(v1); }
                if (sizeof(OT) == 2) {
                    __half2 hv = __floats2half2_rn(v0, v1);
                    *(uint32_t*)((__half*)C + off) = *(uint32_t*)&hv;
                } else {
                    float2 o; o.x = v0; o.y = v1;
                    *(float2*)((float*)C + off) = o;
                }
            }
        }
    }
}

template<bool DO_GELU, bool DO_RES, typename OT>
__global__ void __launch_bounds__(128, 2) hgemm(
    const __half* __restrict__ A, const __half* __restrict__ BT,
    const float* __restrict__ bias, const __half* __restrict__ res,
    OT* __restrict__ C, int N, int K)
{
    extern __shared__ char dsm[];
    hgemm_body<DO_GELU, DO_RES, OT>(A, BT, bias, res, C, N, K,
                                    blockIdx.y * 128, blockIdx.x * 128, dsm);
}

// dual GEMM: flattened 1D grid covering kv-proj + q-proj
struct DP {
    const __half *A1, *B1; const float* bias1; __half* C1; int N1, K1, ntiles1, nx1;
    const __half *A2, *B2; const float* bias2; __half* C2; int N2, K2, nx2;
};
__global__ void __launch_bounds__(128, 2) hgemm_dual(DP p)
{
    extern __shared__ char dsm[];
    int t = blockIdx.x;
    if (t < p.ntiles1) {
        hgemm_body<false, false, __half>(p.A1, p.B1, p.bias1, nullptr, p.C1, p.N1, p.K1,
                                         (t / p.nx1) << 7, (t % p.nx1) << 7, dsm);
    } else {
        t -= p.ntiles1;
        hgemm_body<false, false, __half>(p.A2, p.B2, p.bias2, nullptr, p.C2, p.N2, p.K2,
                                         (t / p.nx2) << 7, (t % p.nx2) << 7, dsm);
    }
}

// ---------------- fp16 flash attention (Q pre-scaled by 1/8 at fill — exact) ----------------
__global__ void __launch_bounds__(256) attn_mma(
    const __half* __restrict__ Q, const __half* __restrict__ KV, __half* __restrict__ O)
{
    extern __shared__ char asm_[];
    const uint32_t Qs = smem_u32(asm_) + AQ_B;
    const uint32_t Ps = smem_u32(asm_) + AP_B;
    const uint32_t Ks = smem_u32(asm_) + AK_B;
    const uint32_t Vs = smem_u32(asm_) + AV_B;

    const int idx = blockIdx.x;
    const int h = idx & 7;
    const int bt = idx >> 3;
    const int b = bt / T_;
    const int tid = threadIdx.x, warp = tid >> 5, lane = tid & 31;
    const int g = lane >> 2, q = lane & 3;
    const int wm = warp * 32;

    {
        const __half* gq = Q + (size_t)(b * NF_) * E_ + h * DH_;
        const __half2 sc = __half2half2(__float2half(0.125f));
        #pragma unroll
        for (int i = tid; i < 256 * 8; i += 256) {
            int r = i >> 3, gg2 = i & 7;
            uint4 v = *(const uint4*)(gq + (size_t)r * E_ + gg2 * 8);
            __half2* hv = (__half2*)&v;
            #pragma unroll
            for (int j = 0; j < 4; j++) hv[j] = __hmul2(hv[j], sc);
            *(uint4*)(asm_ + AQ_B + r * 128 + ((gg2 ^ (r & 7)) << 4)) = v;
        }
    }

    const __half* kvbase = KV + (size_t)bt * NF_ * 1024 + h * DH_;
    auto fillkv = [&](int ch) {
        int st = ch & 1;
        #pragma unroll
        for (int i = tid; i < 64 * 8; i += 256) {
            int r = i >> 3, gk = i & 7;
            const __half* src = kvbase + (size_t)(ch * 64 + r) * 1024 + gk * 8;
            uint32_t so = (uint32_t)(st * 8192 + r * 128 + ((gk ^ (r & 7)) << 4));
            cp16(Ks + so, src);
            cp16(Vs + so, src + 512);
        }
        asm volatile("cp.async.commit_group;" ::: "memory");
    };

    fillkv(0);

    float o[2][8][4];
    #pragma unroll
    for (int mi = 0; mi < 2; mi++)
        #pragma unroll
        for (int nd = 0; nd < 8; nd++)
            #pragma unroll
            for (int r = 0; r < 4; r++) o[mi][nd][r] = 0.0f;
    float mrow[2][2] = {{-1e30f, -1e30f}, {-1e30f, -1e30f}};
    float lrow[2][2] = {{0.0f, 0.0f}, {0.0f, 0.0f}};

    for (int ch = 0; ch < 4; ch++) {
        asm volatile("cp.async.wait_group 0;" ::: "memory");
        __syncthreads();
        if (ch + 1 < 4) fillkv(ch + 1);

        const uint32_t Kst = Ks + (ch & 1) * 8192;
        const uint32_t Vst = Vs + (ch & 1) * 8192;

        float s[2][8][4];
        #pragma unroll
        for (int mi = 0; mi < 2; mi++)
            #pragma unroll
            for (int ni = 0; ni < 8; ni++)
                #pragma unroll
                for (int r = 0; r < 4; r++) s[mi][ni][r] = 0.0f;

        #pragma unroll
        for (int ks = 0; ks < 4; ks++) {
            uint32_t af[2][4], bq[4][4];
            #pragma unroll
            for (int mi = 0; mi < 2; mi++) {
                int row = wm + mi * 16 + (lane & 15);
                uint32_t kg = (uint32_t)(ks * 2 + (lane >> 4));
                ldsm4(af[mi], Qs + (uint32_t)row * 128 + ((kg ^ (row & 7)) << 4));
            }
            #pragma unroll
            for (int nt = 0; nt < 4; nt++) {
                int nr = nt * 16 + ((lane >> 4) << 3) + (lane & 7);
                uint32_t kg = (uint32_t)(ks * 2 + ((lane >> 3) & 1));
                ldsm4(bq[nt], Kst + (uint32_t)nr * 128 + ((kg ^ (nr & 7)) << 4));
            }
            #pragma unroll
            for (int mi = 0; mi < 2; mi++)
                #pragma unroll
                for (int ni = 0; ni < 8; ni++)
                    mma_f16(s[mi][ni], af[mi],
                            bq[ni >> 1][(ni & 1) * 2], bq[ni >> 1][(ni & 1) * 2 + 1]);
        }

        #pragma unroll
        for (int mi = 0; mi < 2; mi++) {
            #pragma unroll
            for (int hh = 0; hh < 2; hh++) {
                float rm = -1e30f;
                #pragma unroll
                for (int ni = 0; ni < 8; ni++)
                    rm = fmaxf(rm, fmaxf(s[mi][ni][hh * 2], s[mi][ni][hh * 2 + 1]));
                rm = fmaxf(rm, __shfl_xor_sync(0xffffffffu, rm, 1));
                rm = fmaxf(rm, __shfl_xor_sync(0xffffffffu, rm, 2));
                float mnew = fmaxf(mrow[mi][hh], rm);
                float alpha = __expf(mrow[mi][hh] - mnew);
                mrow[mi][hh] = mnew;
                float rs = 0.0f;
                #pragma unroll
                for (int ni = 0; ni < 8; ni++) {
                    float p0 = __expf(s[mi][ni][hh * 2]     - mnew);
                    float p1 = __expf(s[mi][ni][hh * 2 + 1] - mnew);
                    rs += p0 + p1;
                    s[mi][ni][hh * 2]     = p0;
                    s[mi][ni][hh * 2 + 1] = p1;
                }
                rs += __shfl_xor_sync(0xffffffffu, rs, 1);
                rs += __shfl_xor_sync(0xffffffffu, rs, 2);
                lrow[mi][hh] = lrow[mi][hh] * alpha + rs;
                #pragma unroll
                for (int nd = 0; nd < 8; nd++) {
                    o[mi][nd][hh * 2]     *= alpha;
                    o[mi][nd][hh * 2 + 1] *= alpha;
                }
            }
        }

        __syncwarp();
        #pragma unroll
        for (int mi = 0; mi < 2; mi++) {
            #pragma unroll
            for (int ni = 0; ni < 8; ni++) {
                int row = wm + mi * 16 + g;
                __half2 p01 = __floats2half2_rn(s[mi][ni][0], s[mi][ni][1]);
                __half2 p23 = __floats2half2_rn(s[mi][ni][2], s[mi][ni][3]);
                *(uint32_t*)(asm_ + AP_B + row * 128 + (((uint32_t)ni ^ (row & 7)) << 4) + q * 4)
                    = *(uint32_t*)&p01;
                int row2 = row + 8;
                *(uint32_t*)(asm_ + AP_B + row2 * 128 + (((uint32_t)ni ^ (row2 & 7)) << 4) + q * 4)
                    = *(uint32_t*)&p23;
            }
        }
        __syncwarp();

        #pragma unroll
        for (int ks = 0; ks < 4; ks++) {
            uint32_t af[2][4], bv[4][4];
            #pragma unroll
            for (int mi = 0; mi < 2; mi++) {
                int row = wm + mi * 16 + (lane & 15);
                uint32_t kg = (uint32_t)(ks * 2 + (lane >> 4));
                ldsm4(af[mi], Ps + (uint32_t)row * 128 + ((kg ^ (row & 7)) << 4));
            }
            #pragma unroll
            for (int nt = 0; nt < 4; nt++) {
                int kr = ks * 16 + (lane & 7) + ((lane >> 3) & 1) * 8;
                uint32_t ng = (uint32_t)(nt * 2 + (lane >> 4));
                ldsm4t(bv[nt], Vst + (uint32_t)kr * 128 + ((ng ^ (kr & 7)) << 4));
            }
            #pragma unroll
            for (int mi = 0; mi < 2; mi++)
                #pragma unroll
                for (int nd = 0; nd < 8; nd++)
                    mma_f16(o[mi][nd], af[mi],
                            bv[nd >> 1][(nd & 1) * 2], bv[nd >> 1][(nd & 1) * 2 + 1]);
        }
        __syncwarp();
    }

    #pragma unroll
    for (int mi = 0; mi < 2; mi++) {
        #pragma unroll
        for (int hh = 0; hh < 2; hh++) {
            float inv = 1.0f / lrow[mi][hh];
            int row = wm + mi * 16 + g + hh * 8;
            __half* orow = O + ((size_t)bt * NF_ + row) * E_ + h * DH_;
            #pragma unroll
            for (int nd = 0; nd < 8; nd++) {
                __half2 ov = __floats2half2_rn(o[mi][nd][hh * 2] * inv,
                                               o[mi][nd][hh * 2 + 1] * inv);
                *(uint32_t*)(orow + nd * 8 + 2 * q) = *(uint32_t*)&ov;
            }
        }
    }
}

// ---------------- host ----------------
extern "C" void kernel_launch(void* const* d_in, const int* in_sizes, int n_in,
                              void* d_out, int out_size)
{
    const float* inputs  = (const float*)d_in[0];
    const float* wq      = (const float*)d_in[1];
    const float* wk      = (const float*)d_in[2];
    const float* wv      = (const float*)d_in[3];
    const float* bq      = (const float*)d_in[4];
    const float* bk      = (const float*)d_in[5];
    const float* bv      = (const float*)d_in[6];
    const float* wo      = (const float*)d_in[7];
    const float* bo      = (const float*)d_in[8];
    const float* lnq_g   = (const float*)d_in[9];
    const float* lnq_b   = (const float*)d_in[10];
    const float* lnkv_g  = (const float*)d_in[11];
    const float* lnkv_b  = (const float*)d_in[12];
    const float* mlpq_w1 = (const float*)d_in[13];
    const float* mlpq_b1 = (const float*)d_in[14];
    const float* mlpq_w2 = (const float*)d_in[15];
    const float* mlpq_b2 = (const float*)d_in[16];
    const float* resln_g = (const float*)d_in[17];
    const float* resln_b = (const float*)d_in[18];
    const float* ln2_g   = (const float*)d_in[19];
    const float* ln2_b   = (const float*)d_in[20];
    const float* mlp_w1  = (const float*)d_in[21];
    const float* mlp_b1  = (const float*)d_in[22];
    const float* mlp_w2  = (const float*)d_in[23];
    const float* mlp_b2  = (const float*)d_in[24];
    float* out = (float*)d_out;

    __half *qln, *q, *kvln, *kv, *t1h, *t2h, *hid, *wtA, *wtB, *wqT;
    float *bkvC;
    cudaGetSymbolAddress((void**)&qln,  g_qln);
    cudaGetSymbolAddress((void**)&q,    g_q);
    cudaGetSymbolAddress((void**)&kvln, g_kvln);
    cudaGetSymbolAddress((void**)&kv,   g_kv);
    cudaGetSymbolAddress((void**)&t1h,  g_t1h);
    cudaGetSymbolAddress((void**)&t2h,  g_t2h);
    cudaGetSymbolAddress((void**)&hid,  g_hid);
    cudaGetSymbolAddress((void**)&wtA,  g_wtA);
    cudaGetSymbolAddress((void**)&wtB,  g_wtB);
    cudaGetSymbolAddress((void**)&wqT,  g_wqT);
    cudaGetSymbolAddress((void**)&bkvC, g_bkv);

    __half* wkvT = wtA;
    __half* woT  = wtA + (size_t)2 * E_ * E_;
    __half* mq1T = wtB;
    __half* mq2T = wtB + (size_t)E_ * M_;
    __half* m1T  = wtB + (size_t)2 * E_ * M_;
    __half* m2T  = wtB + (size_t)3 * E_ * M_;

    cudaFuncSetAttribute(hgemm<false,false,__half>, cudaFuncAttributeMaxDynamicSharedMemorySize, SMEM_TOTAL);
    cudaFuncSetAttribute(hgemm<true ,false,__half>, cudaFuncAttributeMaxDynamicSharedMemorySize, SMEM_TOTAL);
    cudaFuncSetAttribute(hgemm<false,true ,__half>, cudaFuncAttributeMaxDynamicSharedMemorySize, SMEM_TOTAL);
    cudaFuncSetAttribute(hgemm<false,false,float >, cudaFuncAttributeMaxDynamicSharedMemorySize, SMEM_TOTAL);
    cudaFuncSetAttribute(hgemm_dual, cudaFuncAttributeMaxDynamicSharedMemorySize, SMEM_TOTAL);
    cudaFuncSetAttribute(attn_mma, cudaFuncAttributeMaxDynamicSharedMemorySize, ATTN_SMEM);

    PreDesc pd;
    int off = 0;
    auto seg = [&](int i, const float* W, __half* WT, int K, int N) {
        pd.s[i].W = W; pd.s[i].WT = WT; pd.s[i].K = K; pd.s[i].N = N; pd.s[i].blk0 = off;
        off += (N / 32) * (K / 32);
    };
    seg(0, wk,      wkvT,                    E_, E_);
    seg(1, wv,      wkvT + (size_t)E_ * E_,  E_, E_);
    seg(2, wq,      wqT,                     E_, E_);
    seg(3, wo,      woT,                     E_, E_);
    seg(4, mlpq_w1, mq1T,                    E_, M_);
    seg(5, mlpq_w2, mq2T,                    M_, E_);
    seg(6, mlp_w1,  m1T,                     E_, M_);
    seg(7, mlp_w2,  m2T,                     M_, E_);
    pd.bk = bk; pd.bv = bv; pd.bkvO = bkvC;
    pd.X = inputs; pd.gq = lnq_g; pd.bq = lnq_b; pd.gkv = lnkv_g; pd.bkvLN = lnkv_b;
    pd.out_q = qln; pd.out_kv = kvln;
    const int nblk_t = off;                         // 5120

    DP dp;
    dp.A1 = kvln; dp.B1 = wkvT; dp.bias1 = bkvC; dp.C1 = kv;
    dp.N1 = 1024; dp.K1 = E_; dp.nx1 = 1024 / 128;
    dp.ntiles1 = (ROWS_KV / 128) * dp.nx1;          // 3968
    dp.A2 = qln; dp.B2 = wqT; dp.bias2 = bq; dp.C2 = q;
    dp.N2 = E_; dp.K2 = E_; dp.nx2 = E_ / 128;
    const int ntiles2 = (ROWS_Q / 128) * dp.nx2;    // 16

    // 1) fused pre-work
    pre_all<<<nblk_t + 1 + B_ * HW_ * NF_, 256>>>(pd, nblk_t);
    // 2) kv + q projections in one launch
    hgemm_dual<<<dp.ntiles1 + ntiles2, 128, SMEM_TOTAL>>>(dp);
    // 3) attention -> t1h
    attn_mma<<<B_ * T_ * H_, 256, ATTN_SMEM>>>(q, kv, t1h);
    // 4) out projection: t1h -> t2h
    hgemm<false,false,__half><<<dim3(E_/128, ROWS_KV/128), 128, SMEM_TOTAL>>>(t1h, woT, bo, nullptr, t2h, E_, E_);
    // 5-6) mlp_q: t2h -> hid (GELU) -> t1h (fp16, + residual kvln)
    hgemm<true ,false,__half><<<dim3(M_/128, ROWS_KV/128), 128, SMEM_TOTAL>>>(t2h, mq1T, mlpq_b1, nullptr, hid, M_, E_);
    hgemm<false,true ,__half><<<dim3(E_/128, ROWS_KV/128), 128, SMEM_TOTAL>>>(hid, mq2T, mlpq_b2, kvln,  t1h, E_, M_);
    // 7) res_ln + ln_2 fused: t1h -> t2h
    dual_ln_kernel<<<ROWS_KV, 128>>>(t1h, resln_g, resln_b, ln2_g, ln2_b, t2h);
    // 8-9) final MLP: t2h -> hid (GELU) -> out (fp32)
    hgemm<true ,false,__half><<<dim3(M_/128, ROWS_KV/128), 128, SMEM_TOTAL>>>(t2h, m1T, mlp_b1, nullptr, hid, M_, E_);
    hgemm<false,false,float ><<<dim3(E_/128, ROWS_KV/128), 128, SMEM_TOTAL>>>(hid, m2T, mlp_b2, nullptr, out, E_, M_);
}